// round 1
// baseline (speedup 1.0000x reference)
#include <cuda_runtime.h>
#include <math.h>

// Problem dims (fixed by the reference)
#define Bdim 4096
#define Hdim 2048
#define Ndim 8192   // 4*H
#define Kdim 2048

// GEMM tiling
#define BM 128
#define BN 128
#define BK 16
#define TM 8
#define TN 8
#define PAD 4

// Scratch for z = h @ W^T + b  (128 MB) — static device array (no allocs allowed)
__device__ float g_z[(size_t)Bdim * (size_t)Ndim];

// ---------------------------------------------------------------------------
// Kernel 1: z[M,N] = A[M,K] @ B[N,K]^T + bias[N]
// Double-buffered smem, 8x8 per-thread microtile, 256 threads.
// ---------------------------------------------------------------------------
__global__ __launch_bounds__(256) void gemm_bias_kernel(
    const float* __restrict__ A,     // h  [M,K]
    const float* __restrict__ B,     // W  [N,K]
    const float* __restrict__ bias,  // [N]
    float* __restrict__ C)           // z  [M,N]
{
    __shared__ float As[2][BK][BM + PAD];
    __shared__ float Bs[2][BK][BN + PAD];

    const int tid = threadIdx.x;
    const int tx  = tid & 15;          // 0..15 -> N microtile
    const int ty  = tid >> 4;          // 0..15 -> M microtile
    const int bm  = blockIdx.y * BM;
    const int bn  = blockIdx.x * BN;

    const float* Ab = A + (size_t)bm * Kdim;
    const float* Bb = B + (size_t)bn * Kdim;

    // Global->smem load mapping: 128 rows x 16 cols (4 float4 per row)
    const int lrow = tid >> 2;         // 0..63 (two passes: +0, +64)
    const int lcol = (tid & 3) * 4;    // 0,4,8,12

    float acc[TM][TN];
#pragma unroll
    for (int i = 0; i < TM; i++)
#pragma unroll
        for (int j = 0; j < TN; j++) acc[i][j] = 0.f;

    // --- load tile 0 into buffer 0 ---
    {
        float4 a0 = *(const float4*)(Ab + (size_t)lrow * Kdim + lcol);
        float4 a1 = *(const float4*)(Ab + (size_t)(lrow + 64) * Kdim + lcol);
        float4 b0 = *(const float4*)(Bb + (size_t)lrow * Kdim + lcol);
        float4 b1 = *(const float4*)(Bb + (size_t)(lrow + 64) * Kdim + lcol);
        As[0][lcol + 0][lrow] = a0.x; As[0][lcol + 1][lrow] = a0.y;
        As[0][lcol + 2][lrow] = a0.z; As[0][lcol + 3][lrow] = a0.w;
        As[0][lcol + 0][lrow + 64] = a1.x; As[0][lcol + 1][lrow + 64] = a1.y;
        As[0][lcol + 2][lrow + 64] = a1.z; As[0][lcol + 3][lrow + 64] = a1.w;
        Bs[0][lcol + 0][lrow] = b0.x; Bs[0][lcol + 1][lrow] = b0.y;
        Bs[0][lcol + 2][lrow] = b0.z; Bs[0][lcol + 3][lrow] = b0.w;
        Bs[0][lcol + 0][lrow + 64] = b1.x; Bs[0][lcol + 1][lrow + 64] = b1.y;
        Bs[0][lcol + 2][lrow + 64] = b1.z; Bs[0][lcol + 3][lrow + 64] = b1.w;
    }
    __syncthreads();

    const int NT = Kdim / BK;   // 128
    int cur = 0;

    for (int t = 0; t < NT; t++) {
        float4 pa0, pa1, pb0, pb1;
        const bool has_next = (t + 1 < NT);
        if (has_next) {
            const int k0 = (t + 1) * BK;
            pa0 = *(const float4*)(Ab + (size_t)lrow * Kdim + k0 + lcol);
            pa1 = *(const float4*)(Ab + (size_t)(lrow + 64) * Kdim + k0 + lcol);
            pb0 = *(const float4*)(Bb + (size_t)lrow * Kdim + k0 + lcol);
            pb1 = *(const float4*)(Bb + (size_t)(lrow + 64) * Kdim + k0 + lcol);
        }

#pragma unroll
        for (int k = 0; k < BK; k++) {
            float af[TM], bf[TN];
            float4 a04 = *(const float4*)&As[cur][k][ty * TM];
            float4 a14 = *(const float4*)&As[cur][k][ty * TM + 4];
            float4 b04 = *(const float4*)&Bs[cur][k][tx * TN];
            float4 b14 = *(const float4*)&Bs[cur][k][tx * TN + 4];
            af[0]=a04.x; af[1]=a04.y; af[2]=a04.z; af[3]=a04.w;
            af[4]=a14.x; af[5]=a14.y; af[6]=a14.z; af[7]=a14.w;
            bf[0]=b04.x; bf[1]=b04.y; bf[2]=b04.z; bf[3]=b04.w;
            bf[4]=b14.x; bf[5]=b14.y; bf[6]=b14.z; bf[7]=b14.w;
#pragma unroll
            for (int i = 0; i < TM; i++)
#pragma unroll
                for (int j = 0; j < TN; j++)
                    acc[i][j] = fmaf(af[i], bf[j], acc[i][j]);
        }

        if (has_next) {
            const int nxt = cur ^ 1;
            As[nxt][lcol + 0][lrow] = pa0.x; As[nxt][lcol + 1][lrow] = pa0.y;
            As[nxt][lcol + 2][lrow] = pa0.z; As[nxt][lcol + 3][lrow] = pa0.w;
            As[nxt][lcol + 0][lrow + 64] = pa1.x; As[nxt][lcol + 1][lrow + 64] = pa1.y;
            As[nxt][lcol + 2][lrow + 64] = pa1.z; As[nxt][lcol + 3][lrow + 64] = pa1.w;
            Bs[nxt][lcol + 0][lrow] = pb0.x; Bs[nxt][lcol + 1][lrow] = pb0.y;
            Bs[nxt][lcol + 2][lrow] = pb0.z; Bs[nxt][lcol + 3][lrow] = pb0.w;
            Bs[nxt][lcol + 0][lrow + 64] = pb1.x; Bs[nxt][lcol + 1][lrow + 64] = pb1.y;
            Bs[nxt][lcol + 2][lrow + 64] = pb1.z; Bs[nxt][lcol + 3][lrow + 64] = pb1.w;
        }
        __syncthreads();
        cur ^= 1;
    }

    // Epilogue: add bias, store (vectorized)
    const int n0 = bn + tx * TN;
    float4 bv0 = *(const float4*)(bias + n0);
    float4 bv1 = *(const float4*)(bias + n0 + 4);
#pragma unroll
    for (int i = 0; i < TM; i++) {
        const size_t row = (size_t)(bm + ty * TM + i) * Ndim;
        float4 o0, o1;
        o0.x = acc[i][0] + bv0.x; o0.y = acc[i][1] + bv0.y;
        o0.z = acc[i][2] + bv0.z; o0.w = acc[i][3] + bv0.w;
        o1.x = acc[i][4] + bv1.x; o1.y = acc[i][5] + bv1.y;
        o1.z = acc[i][6] + bv1.z; o1.w = acc[i][7] + bv1.w;
        *(float4*)(C + row + n0)     = o0;
        *(float4*)(C + row + n0 + 4) = o1;
    }
}

// ---------------------------------------------------------------------------
// Kernel 2: per-row GroupNorm(4 groups of 2048) + LSTM gates
// out[0 : B*H)      = h_new
// out[B*H : 2*B*H)  = c_new
// ---------------------------------------------------------------------------
__device__ __forceinline__ float sigmoidf_(float x) {
    return 1.f / (1.f + expf(-x));
}

__global__ __launch_bounds__(256) void gn_gates_kernel(
    const float* __restrict__ z,    // [B, 4H]
    const float* __restrict__ cin,  // [B, H]
    const float* __restrict__ gw,   // [4H]
    const float* __restrict__ gb,   // [4H]
    float* __restrict__ out)        // [2*B*H]
{
    const int r = blockIdx.x;
    const int t = threadIdx.x;
    const float4* z4 = (const float4*)(z + (size_t)r * Ndim);  // 2048 float4 per row

    // --- Phase 1: per-group mean/var. group g owns float4 [g*512, (g+1)*512) ---
    const int g    = t >> 6;   // 0..3
    const int lane = t & 63;   // 0..63
    float s = 0.f, ss = 0.f;
#pragma unroll
    for (int i = 0; i < 8; i++) {
        float4 v = z4[g * 512 + lane + i * 64];
        s  += v.x + v.y + v.z + v.w;
        ss += v.x * v.x + v.y * v.y + v.z * v.z + v.w * v.w;
    }
    __shared__ float red_s[256], red_q[256];
    red_s[t] = s; red_q[t] = ss;
    __syncthreads();
#pragma unroll
    for (int off = 32; off >= 1; off >>= 1) {
        if (lane < off) {
            red_s[t] += red_s[t + off];
            red_q[t] += red_q[t + off];
        }
        __syncthreads();
    }
    __shared__ float s_mean[4], s_rstd[4];
    if (t < 4) {
        float m = red_s[t * 64] * (1.f / 2048.f);
        float v = red_q[t * 64] * (1.f / 2048.f) - m * m;
        s_mean[t] = m;
        s_rstd[t] = rsqrtf(v + 1e-5f);
    }
    __syncthreads();

    const float mi = s_mean[0], ri = s_rstd[0];
    const float mf = s_mean[1], rf = s_rstd[1];
    const float mo = s_mean[2], ro = s_rstd[2];
    const float mg = s_mean[3], rg = s_rstd[3];

    const float4* c4  = (const float4*)(cin + (size_t)r * Hdim);
    const float4* gw4 = (const float4*)gw;
    const float4* gb4 = (const float4*)gb;
    float4* h4  = (float4*)out + (size_t)r * (Hdim / 4);
    float4* cn4 = (float4*)out + (size_t)Bdim * (Hdim / 4) + (size_t)r * (Hdim / 4);

    // --- Phase 2: gates, 2 float4 per thread (512 float4 per row) ---
#pragma unroll
    for (int p = 0; p < 2; p++) {
        const int j4 = t + p * 256;   // 0..511
        float4 zi = z4[j4];
        float4 zf = z4[512 + j4];
        float4 zo = z4[1024 + j4];
        float4 zg = z4[1536 + j4];
        float4 wi = gw4[j4],        bi = gb4[j4];
        float4 wf = gw4[512 + j4],  bf2 = gb4[512 + j4];
        float4 wo = gw4[1024 + j4], bo = gb4[1024 + j4];
        float4 wg = gw4[1536 + j4], bg = gb4[1536 + j4];
        float4 cv = c4[j4];

        float4 hn, cn;
#define GATE(comp)                                                            \
        {                                                                     \
            float vi = (zi.comp - mi) * ri * wi.comp + bi.comp;               \
            float vf = (zf.comp - mf) * rf * wf.comp + bf2.comp;              \
            float vo = (zo.comp - mo) * ro * wo.comp + bo.comp;               \
            float vg = (zg.comp - mg) * rg * wg.comp + bg.comp;               \
            float cnew = sigmoidf_(vf) * cv.comp + sigmoidf_(vi) * tanhf(vg); \
            cn.comp = cnew;                                                   \
            hn.comp = sigmoidf_(vo) * tanhf(cnew);                            \
        }
        GATE(x); GATE(y); GATE(z); GATE(w);
#undef GATE
        h4[j4]  = hn;
        cn4[j4] = cn;
    }
}

// ---------------------------------------------------------------------------
extern "C" void kernel_launch(void* const* d_in, const int* in_sizes, int n_in,
                              void* d_out, int out_size)
{
    // metadata order: x(0, unused), h(1), c(2), W(3), b(4), gn_weight(5), gn_bias(6)
    const float* h  = (const float*)d_in[1];
    const float* c  = (const float*)d_in[2];
    const float* W  = (const float*)d_in[3];
    const float* b  = (const float*)d_in[4];
    const float* gw = (const float*)d_in[5];
    const float* gb = (const float*)d_in[6];
    float* out = (float*)d_out;

    float* z;
    cudaGetSymbolAddress((void**)&z, g_z);

    dim3 ggrid(Ndim / BN, Bdim / BM);   // (64, 32)
    gemm_bias_kernel<<<ggrid, 256>>>(h, W, b, z);
    gn_gates_kernel<<<Bdim, 256>>>(z, c, gw, gb, out);
}

// round 3
// speedup vs baseline: 2.1288x; 2.1288x over previous
#include <cuda_runtime.h>
#include <cuda_bf16.h>
#include <math.h>
#include <stdint.h>

// ---------------------------------------------------------------------------
// Problem dims
#define Bdim 4096
#define Hdim 2048
#define Ndim 8192   // 4*H
#define Kdim 2048

// GEMM tiling
#define BM 128
#define BN 128
#define BK 32
#define STAGES 4
#define NT (Kdim / BK)      // 64

// SMEM stage layout: 4 arrays of [128 rows][40 bf16] (pad 32->40 for conflict-free ldmatrix)
#define RS   40
#define RSB  80             // bytes per row
#define STG_A_HI 0
#define STG_A_LO 10240
#define STG_B_HI 20480
#define STG_B_LO 30720
#define STG_SIZE 40960
#define SMEM_TOTAL (STAGES * STG_SIZE)   // 163840

// Scratch (static device arrays; no runtime allocation allowed)
__device__ float         g_z  [(size_t)Bdim * Ndim];
__device__ __nv_bfloat16 g_Ahi[(size_t)Bdim * Kdim];
__device__ __nv_bfloat16 g_Alo[(size_t)Bdim * Kdim];
__device__ __nv_bfloat16 g_Bhi[(size_t)Ndim * Kdim];
__device__ __nv_bfloat16 g_Blo[(size_t)Ndim * Kdim];

// ---------------------------------------------------------------------------
__device__ __forceinline__ uint32_t smem_u32(const void* p) {
    uint32_t a;
    asm("{ .reg .u64 t; cvta.to.shared.u64 t, %1; cvt.u32.u64 %0, t; }" : "=r"(a) : "l"(p));
    return a;
}
__device__ __forceinline__ void cp16(uint32_t dst, const void* src) {
    asm volatile("cp.async.cg.shared.global [%0], [%1], 16;\n" :: "r"(dst), "l"(src) : "memory");
}
#define CP_COMMIT()  asm volatile("cp.async.commit_group;" ::: "memory")
#define CP_WAIT(n)   asm volatile("cp.async.wait_group %0;" :: "n"(n) : "memory")

#define LDSM4(r0, r1, r2, r3, addr)                                           \
    asm volatile("ldmatrix.sync.aligned.m8n8.x4.shared.b16 {%0,%1,%2,%3},[%4];" \
        : "=r"(r0), "=r"(r1), "=r"(r2), "=r"(r3) : "r"(addr))

#define MMA_BF16(d, a, b0, b1)                                                \
    asm volatile("mma.sync.aligned.m16n8k16.row.col.f32.bf16.bf16.f32 "       \
        "{%0,%1,%2,%3},{%4,%5,%6,%7},{%8,%9},{%0,%1,%2,%3};"                  \
        : "+f"((d)[0]), "+f"((d)[1]), "+f"((d)[2]), "+f"((d)[3])              \
        : "r"((a)[0]), "r"((a)[1]), "r"((a)[2]), "r"((a)[3]),                 \
          "r"(b0), "r"(b1))

// ---------------------------------------------------------------------------
// Kernel 0: split fp32 -> (bf16 hi, bf16 lo)
// ---------------------------------------------------------------------------
__global__ __launch_bounds__(256) void split_bf16_kernel(
    const float* __restrict__ x, __nv_bfloat16* __restrict__ hi,
    __nv_bfloat16* __restrict__ lo, int n4)
{
    int i = blockIdx.x * blockDim.x + threadIdx.x;
    if (i >= n4) return;
    float4 v = ((const float4*)x)[i];
    __nv_bfloat162 h01, h23, l01, l23;
    __nv_bfloat16 t;
    t = __float2bfloat16(v.x); h01.x = t; l01.x = __float2bfloat16(v.x - __bfloat162float(t));
    t = __float2bfloat16(v.y); h01.y = t; l01.y = __float2bfloat16(v.y - __bfloat162float(t));
    t = __float2bfloat16(v.z); h23.x = t; l23.x = __float2bfloat16(v.z - __bfloat162float(t));
    t = __float2bfloat16(v.w); h23.y = t; l23.y = __float2bfloat16(v.w - __bfloat162float(t));
    ((__nv_bfloat162*)hi)[2 * i]     = h01;
    ((__nv_bfloat162*)hi)[2 * i + 1] = h23;
    ((__nv_bfloat162*)lo)[2 * i]     = l01;
    ((__nv_bfloat162*)lo)[2 * i + 1] = l23;
}

// ---------------------------------------------------------------------------
// Kernel 1: z[M,N] = (Ahi+Alo)[M,K] @ (Bhi+Blo)[N,K]^T + bias
// mma.sync.m16n8k16 bf16, fp32 accum; hi*hi + hi*lo + lo*hi (lo*lo dropped).
// 256 threads = 8 warps in 4(M) x 2(N); per warp 32x64.
// ---------------------------------------------------------------------------
__global__ __launch_bounds__(256, 1) void gemm_tc_kernel(
    const __nv_bfloat16* __restrict__ Ahi, const __nv_bfloat16* __restrict__ Alo,
    const __nv_bfloat16* __restrict__ Bhi, const __nv_bfloat16* __restrict__ Blo,
    const float* __restrict__ bias, float* __restrict__ Z)
{
    extern __shared__ char smem[];
    const uint32_t sb = smem_u32(smem);

    const int tid    = threadIdx.x;
    const int lane   = tid & 31;
    const int wid    = tid >> 5;
    const int warp_m = wid & 3;     // 0..3 -> 32 rows each
    const int warp_n = wid >> 2;    // 0..1 -> 64 cols each
    const int bm     = blockIdx.y * BM;
    const int bn     = blockIdx.x * BN;

    const char* Agh = (const char*)(Ahi + (size_t)bm * Kdim);
    const char* Agl = (const char*)(Alo + (size_t)bm * Kdim);
    const char* Bgh = (const char*)(Bhi + (size_t)bn * Kdim);
    const char* Bgl = (const char*)(Blo + (size_t)bn * Kdim);

    // cp.async mapping: 4 chunks of 16B per 64B row, 256 threads -> 64 rows/pass
    const int lc = (tid & 3) * 16;
    const int lr = tid >> 2;

    // ldmatrix per-lane offsets (byte offsets within a stage, stage base added later)
    // A (x4): lanes 0-15 rows m0-15 (k 0-7), lanes 16-31 same rows (k 8-15)
    uint32_t offA[2];
#pragma unroll
    for (int mt = 0; mt < 2; mt++)
        offA[mt] = (uint32_t)((warp_m * 32 + mt * 16 + (lane & 15)) * RSB + (lane >> 4) * 16);
    // B (x4 covers 2 n-tiles): lanes 0-7 n0-7/k0-7, 8-15 n0-7/k8-15, 16-23 n8-15/k0-7, 24-31 n8-15/k8-15
    uint32_t offB[4];
#pragma unroll
    for (int pr = 0; pr < 4; pr++)
        offB[pr] = (uint32_t)((warp_n * 64 + pr * 16 + (lane & 7) + ((lane >> 4) & 1) * 8) * RSB
                              + ((lane >> 3) & 1) * 16);

    float acc[2][8][4];
#pragma unroll
    for (int mt = 0; mt < 2; mt++)
#pragma unroll
        for (int nt = 0; nt < 8; nt++)
#pragma unroll
            for (int q = 0; q < 4; q++) acc[mt][nt][q] = 0.f;

    // -------- pipeline prologue: load stages 0..STAGES-2 --------
#pragma unroll
    for (int t = 0; t < STAGES - 1; t++) {
        const uint32_t st = sb + t * STG_SIZE;
        const size_t kb = (size_t)t * (BK * 2);
        int r = lr;
#pragma unroll
        for (int p = 0; p < 2; p++, r += 64) {
            const size_t go = (size_t)r * (Kdim * 2) + kb + lc;
            const uint32_t so = r * RSB + lc;
            cp16(st + STG_A_HI + so, Agh + go);
            cp16(st + STG_A_LO + so, Agl + go);
            cp16(st + STG_B_HI + so, Bgh + go);
            cp16(st + STG_B_LO + so, Bgl + go);
        }
        CP_COMMIT();
    }

    // -------- main loop --------
    for (int t = 0; t < NT; t++) {
        CP_WAIT(STAGES - 2);
        __syncthreads();

        // issue loads for stage t+STAGES-1 (overwrites stage computed at t-1)
        const int tn = t + STAGES - 1;
        if (tn < NT) {
            const uint32_t st = sb + (tn % STAGES) * STG_SIZE;
            const size_t kb = (size_t)tn * (BK * 2);
            int r = lr;
#pragma unroll
            for (int p = 0; p < 2; p++, r += 64) {
                const size_t go = (size_t)r * (Kdim * 2) + kb + lc;
                const uint32_t so = r * RSB + lc;
                cp16(st + STG_A_HI + so, Agh + go);
                cp16(st + STG_A_LO + so, Agl + go);
                cp16(st + STG_B_HI + so, Bgh + go);
                cp16(st + STG_B_LO + so, Bgl + go);
            }
        }
        CP_COMMIT();

        // compute stage t
        const uint32_t st = sb + (t % STAGES) * STG_SIZE;
#pragma unroll
        for (int ks = 0; ks < 2; ks++) {
            const uint32_t ko = ks * 32;   // 16 bf16 = 32B along K
            uint32_t ah[2][4], al[2][4];
#pragma unroll
            for (int mt = 0; mt < 2; mt++) {
                LDSM4(ah[mt][0], ah[mt][1], ah[mt][2], ah[mt][3], st + STG_A_HI + offA[mt] + ko);
                LDSM4(al[mt][0], al[mt][1], al[mt][2], al[mt][3], st + STG_A_LO + offA[mt] + ko);
            }
#pragma unroll
            for (int pr = 0; pr < 4; pr++) {
                uint32_t bh[4], bl[4];
                LDSM4(bh[0], bh[1], bh[2], bh[3], st + STG_B_HI + offB[pr] + ko);
                LDSM4(bl[0], bl[1], bl[2], bl[3], st + STG_B_LO + offB[pr] + ko);
#pragma unroll
                for (int sub = 0; sub < 2; sub++) {
                    const int nt = pr * 2 + sub;
#pragma unroll
                    for (int mt = 0; mt < 2; mt++) {
                        MMA_BF16(acc[mt][nt], ah[mt], bh[2 * sub], bh[2 * sub + 1]);
                        MMA_BF16(acc[mt][nt], ah[mt], bl[2 * sub], bl[2 * sub + 1]);
                        MMA_BF16(acc[mt][nt], al[mt], bh[2 * sub], bh[2 * sub + 1]);
                    }
                }
            }
        }
    }

    // -------- epilogue: bias add + store --------
    const int ln4 = lane >> 2;
    const int lq  = lane & 3;
#pragma unroll
    for (int mt = 0; mt < 2; mt++) {
#pragma unroll
        for (int nt = 0; nt < 8; nt++) {
            const int m0 = bm + warp_m * 32 + mt * 16 + ln4;
            const int n  = bn + warp_n * 64 + nt * 8 + lq * 2;
            const float2 bv = *(const float2*)(bias + n);
            float2 o0, o1;
            o0.x = acc[mt][nt][0] + bv.x; o0.y = acc[mt][nt][1] + bv.y;
            o1.x = acc[mt][nt][2] + bv.x; o1.y = acc[mt][nt][3] + bv.y;
            *(float2*)(Z + (size_t)m0 * Ndim + n)       = o0;
            *(float2*)(Z + (size_t)(m0 + 8) * Ndim + n) = o1;
        }
    }
}

// ---------------------------------------------------------------------------
// Kernel 2: per-row GroupNorm(4 groups of 2048) + LSTM gates
// ---------------------------------------------------------------------------
__device__ __forceinline__ float sigmoidf_(float x) {
    return 1.f / (1.f + expf(-x));
}

__global__ __launch_bounds__(256) void gn_gates_kernel(
    const float* __restrict__ z, const float* __restrict__ cin,
    const float* __restrict__ gw, const float* __restrict__ gb,
    float* __restrict__ out)
{
    const int r = blockIdx.x;
    const int t = threadIdx.x;
    const float4* z4 = (const float4*)(z + (size_t)r * Ndim);

    const int g    = t >> 6;
    const int lane = t & 63;
    float s = 0.f, ss = 0.f;
#pragma unroll
    for (int i = 0; i < 8; i++) {
        float4 v = z4[g * 512 + lane + i * 64];
        s  += v.x + v.y + v.z + v.w;
        ss += v.x * v.x + v.y * v.y + v.z * v.z + v.w * v.w;
    }
    __shared__ float red_s[256], red_q[256];
    red_s[t] = s; red_q[t] = ss;
    __syncthreads();
#pragma unroll
    for (int off = 32; off >= 1; off >>= 1) {
        if (lane < off) {
            red_s[t] += red_s[t + off];
            red_q[t] += red_q[t + off];
        }
        __syncthreads();
    }
    __shared__ float s_mean[4], s_rstd[4];
    if (t < 4) {
        float m = red_s[t * 64] * (1.f / 2048.f);
        float v = red_q[t * 64] * (1.f / 2048.f) - m * m;
        s_mean[t] = m;
        s_rstd[t] = rsqrtf(v + 1e-5f);
    }
    __syncthreads();

    const float mi = s_mean[0], ri = s_rstd[0];
    const float mf = s_mean[1], rf = s_rstd[1];
    const float mo = s_mean[2], ro = s_rstd[2];
    const float mg = s_mean[3], rg = s_rstd[3];

    const float4* c4  = (const float4*)(cin + (size_t)r * Hdim);
    const float4* gw4 = (const float4*)gw;
    const float4* gb4 = (const float4*)gb;
    float4* h4  = (float4*)out + (size_t)r * (Hdim / 4);
    float4* cn4 = (float4*)out + (size_t)Bdim * (Hdim / 4) + (size_t)r * (Hdim / 4);

#pragma unroll
    for (int p = 0; p < 2; p++) {
        const int j4 = t + p * 256;
        float4 zi = z4[j4];
        float4 zf = z4[512 + j4];
        float4 zo = z4[1024 + j4];
        float4 zg = z4[1536 + j4];
        float4 wi = gw4[j4],        bi  = gb4[j4];
        float4 wf = gw4[512 + j4],  bf2 = gb4[512 + j4];
        float4 wo = gw4[1024 + j4], bo  = gb4[1024 + j4];
        float4 wg = gw4[1536 + j4], bg  = gb4[1536 + j4];
        float4 cv = c4[j4];

        float4 hn, cn;
#define GATE(comp)                                                            \
        {                                                                     \
            float vi = (zi.comp - mi) * ri * wi.comp + bi.comp;               \
            float vf = (zf.comp - mf) * rf * wf.comp + bf2.comp;              \
            float vo = (zo.comp - mo) * ro * wo.comp + bo.comp;               \
            float vg = (zg.comp - mg) * rg * wg.comp + bg.comp;               \
            float cnew = sigmoidf_(vf) * cv.comp + sigmoidf_(vi) * tanhf(vg); \
            cn.comp = cnew;                                                   \
            hn.comp = sigmoidf_(vo) * tanhf(cnew);                            \
        }
        GATE(x); GATE(y); GATE(z); GATE(w);
#undef GATE
        h4[j4]  = hn;
        cn4[j4] = cn;
    }
}

// ---------------------------------------------------------------------------
extern "C" void kernel_launch(void* const* d_in, const int* in_sizes, int n_in,
                              void* d_out, int out_size)
{
    // metadata order: x(0, unused), h(1), c(2), W(3), b(4), gn_weight(5), gn_bias(6)
    const float* h  = (const float*)d_in[1];
    const float* c  = (const float*)d_in[2];
    const float* W  = (const float*)d_in[3];
    const float* b  = (const float*)d_in[4];
    const float* gw = (const float*)d_in[5];
    const float* gb = (const float*)d_in[6];
    float* out = (float*)d_out;

    float* z;            cudaGetSymbolAddress((void**)&z,   g_z);
    __nv_bfloat16 *Ahi, *Alo, *Bhi, *Blo;
    cudaGetSymbolAddress((void**)&Ahi, g_Ahi);
    cudaGetSymbolAddress((void**)&Alo, g_Alo);
    cudaGetSymbolAddress((void**)&Bhi, g_Bhi);
    cudaGetSymbolAddress((void**)&Blo, g_Blo);

    cudaFuncSetAttribute(gemm_tc_kernel,
                         cudaFuncAttributeMaxDynamicSharedMemorySize, SMEM_TOTAL);

    const int nA4 = Bdim * Kdim / 4;
    const int nB4 = Ndim * Kdim / 4;
    split_bf16_kernel<<<(nA4 + 255) / 256, 256>>>(h, Ahi, Alo, nA4);
    split_bf16_kernel<<<(nB4 + 255) / 256, 256>>>(W, Bhi, Blo, nB4);

    dim3 ggrid(Ndim / BN, Bdim / BM);   // (64, 32)
    gemm_tc_kernel<<<ggrid, 256, SMEM_TOTAL>>>(Ahi, Alo, Bhi, Blo, b, z);

    gn_gates_kernel<<<Bdim, 256>>>(z, c, gw, gb, out);
}

// round 4
// speedup vs baseline: 2.3621x; 1.1096x over previous
#include <cuda_runtime.h>
#include <cuda_bf16.h>
#include <math.h>
#include <stdint.h>

// ---------------------------------------------------------------------------
// Problem dims
#define Bdim 4096
#define Hdim 2048
#define Ndim 8192   // 4*H
#define Kdim 2048

// GEMM tiling
#define BM 128
#define BN 256
#define BK 32
#define STAGES 3
#define NT (Kdim / BK)      // 64

// SMEM stage layout (rows of 40 bf16 = 80B, pad 32->40 for conflict-free ldmatrix)
#define RSB  80
#define STG_A_HI 0
#define STG_A_LO 10240
#define STG_B_HI 20480
#define STG_B_LO 40960
#define STG_SIZE 61440
#define SMEM_TOTAL (STAGES * STG_SIZE)   // 184320

// Scratch (static device arrays; no runtime allocation allowed)
__device__ float         g_z  [(size_t)Bdim * Ndim];
__device__ __nv_bfloat16 g_Ahi[(size_t)Bdim * Kdim];
__device__ __nv_bfloat16 g_Alo[(size_t)Bdim * Kdim];
__device__ __nv_bfloat16 g_Bhi[(size_t)Ndim * Kdim];
__device__ __nv_bfloat16 g_Blo[(size_t)Ndim * Kdim];

// ---------------------------------------------------------------------------
__device__ __forceinline__ uint32_t smem_u32(const void* p) {
    uint32_t a;
    asm("{ .reg .u64 t; cvta.to.shared.u64 t, %1; cvt.u32.u64 %0, t; }" : "=r"(a) : "l"(p));
    return a;
}
__device__ __forceinline__ void cp16(uint32_t dst, const void* src) {
    asm volatile("cp.async.cg.shared.global [%0], [%1], 16;\n" :: "r"(dst), "l"(src) : "memory");
}
#define CP_COMMIT()  asm volatile("cp.async.commit_group;" ::: "memory")
#define CP_WAIT(n)   asm volatile("cp.async.wait_group %0;" :: "n"(n) : "memory")

#define LDSM4(r0, r1, r2, r3, addr)                                           \
    asm volatile("ldmatrix.sync.aligned.m8n8.x4.shared.b16 {%0,%1,%2,%3},[%4];" \
        : "=r"(r0), "=r"(r1), "=r"(r2), "=r"(r3) : "r"(addr))

#define MMA_BF16(d, a, b0, b1)                                                \
    asm volatile("mma.sync.aligned.m16n8k16.row.col.f32.bf16.bf16.f32 "       \
        "{%0,%1,%2,%3},{%4,%5,%6,%7},{%8,%9},{%0,%1,%2,%3};"                  \
        : "+f"((d)[0]), "+f"((d)[1]), "+f"((d)[2]), "+f"((d)[3])              \
        : "r"((a)[0]), "r"((a)[1]), "r"((a)[2]), "r"((a)[3]),                 \
          "r"(b0), "r"(b1))

// ---------------------------------------------------------------------------
// Kernel 0: split fp32 -> (bf16 hi, bf16 lo)
// ---------------------------------------------------------------------------
__global__ __launch_bounds__(256) void split_bf16_kernel(
    const float* __restrict__ x, __nv_bfloat16* __restrict__ hi,
    __nv_bfloat16* __restrict__ lo, int n4)
{
    int i = blockIdx.x * blockDim.x + threadIdx.x;
    if (i >= n4) return;
    float4 v = ((const float4*)x)[i];
    __nv_bfloat162 h01, h23, l01, l23;
    __nv_bfloat16 t;
    t = __float2bfloat16(v.x); h01.x = t; l01.x = __float2bfloat16(v.x - __bfloat162float(t));
    t = __float2bfloat16(v.y); h01.y = t; l01.y = __float2bfloat16(v.y - __bfloat162float(t));
    t = __float2bfloat16(v.z); h23.x = t; l23.x = __float2bfloat16(v.z - __bfloat162float(t));
    t = __float2bfloat16(v.w); h23.y = t; l23.y = __float2bfloat16(v.w - __bfloat162float(t));
    ((__nv_bfloat162*)hi)[2 * i]     = h01;
    ((__nv_bfloat162*)hi)[2 * i + 1] = h23;
    ((__nv_bfloat162*)lo)[2 * i]     = l01;
    ((__nv_bfloat162*)lo)[2 * i + 1] = l23;
}

// ---------------------------------------------------------------------------
// Kernel 1: z[M,N] = (Ahi+Alo)[M,K] @ (Bhi+Blo)[N,K]^T + bias
// mma.sync.m16n8k16 bf16, fp32 accum; hi*hi + hi*lo + lo*hi (lo*lo dropped).
// 512 threads = 16 warps in 4(M) x 4(N); per warp 32x64.
// ---------------------------------------------------------------------------
__global__ __launch_bounds__(512, 1) void gemm_tc_kernel(
    const __nv_bfloat16* __restrict__ Ahi, const __nv_bfloat16* __restrict__ Alo,
    const __nv_bfloat16* __restrict__ Bhi, const __nv_bfloat16* __restrict__ Blo,
    const float* __restrict__ bias, float* __restrict__ Z)
{
    extern __shared__ char smem[];
    const uint32_t sb = smem_u32(smem);

    const int tid    = threadIdx.x;
    const int lane   = tid & 31;
    const int wid    = tid >> 5;
    const int warp_m = wid & 3;     // 0..3 -> 32 rows each
    const int warp_n = wid >> 2;    // 0..3 -> 64 cols each
    const int bm     = blockIdx.y * BM;
    const int bn     = blockIdx.x * BN;

    const char* Agh = (const char*)(Ahi + (size_t)bm * Kdim);
    const char* Agl = (const char*)(Alo + (size_t)bm * Kdim);
    const char* Bgh = (const char*)(Bhi + (size_t)bn * Kdim);
    const char* Bgl = (const char*)(Blo + (size_t)bn * Kdim);

    // cp.async mapping: 512 threads, 4x16B chunks per 64B row -> 128 rows/pass
    const int lc = (tid & 3) * 16;
    const int lr = tid >> 2;        // 0..127

    // ldmatrix per-lane offsets (byte offsets within a stage)
    uint32_t offA[2];
#pragma unroll
    for (int mt = 0; mt < 2; mt++)
        offA[mt] = (uint32_t)((warp_m * 32 + mt * 16 + (lane & 15)) * RSB + (lane >> 4) * 16);
    uint32_t offB[4];
#pragma unroll
    for (int pr = 0; pr < 4; pr++)
        offB[pr] = (uint32_t)((warp_n * 64 + pr * 16 + (lane & 7) + ((lane >> 4) & 1) * 8) * RSB
                              + ((lane >> 3) & 1) * 16);

    float acc[2][8][4];
#pragma unroll
    for (int mt = 0; mt < 2; mt++)
#pragma unroll
        for (int nt = 0; nt < 8; nt++)
#pragma unroll
            for (int q = 0; q < 4; q++) acc[mt][nt][q] = 0.f;

    // -------- pipeline prologue: load stages 0..STAGES-2 --------
#pragma unroll
    for (int t = 0; t < STAGES - 1; t++) {
        const uint32_t st = sb + t * STG_SIZE;
        const size_t kb = (size_t)t * (BK * 2);
        {   // A: 128 rows, one pass
            const size_t go = (size_t)lr * (Kdim * 2) + kb + lc;
            const uint32_t so = lr * RSB + lc;
            cp16(st + STG_A_HI + so, Agh + go);
            cp16(st + STG_A_LO + so, Agl + go);
        }
#pragma unroll
        for (int p = 0; p < 2; p++) {   // B: 256 rows, two passes
            const int r = lr + p * 128;
            const size_t go = (size_t)r * (Kdim * 2) + kb + lc;
            const uint32_t so = r * RSB + lc;
            cp16(st + STG_B_HI + so, Bgh + go);
            cp16(st + STG_B_LO + so, Bgl + go);
        }
        CP_COMMIT();
    }

    // -------- main loop --------
    for (int t = 0; t < NT; t++) {
        CP_WAIT(STAGES - 2);
        __syncthreads();

        const int tn = t + STAGES - 1;
        if (tn < NT) {
            const uint32_t st = sb + (tn % STAGES) * STG_SIZE;
            const size_t kb = (size_t)tn * (BK * 2);
            {
                const size_t go = (size_t)lr * (Kdim * 2) + kb + lc;
                const uint32_t so = lr * RSB + lc;
                cp16(st + STG_A_HI + so, Agh + go);
                cp16(st + STG_A_LO + so, Agl + go);
            }
#pragma unroll
            for (int p = 0; p < 2; p++) {
                const int r = lr + p * 128;
                const size_t go = (size_t)r * (Kdim * 2) + kb + lc;
                const uint32_t so = r * RSB + lc;
                cp16(st + STG_B_HI + so, Bgh + go);
                cp16(st + STG_B_LO + so, Bgl + go);
            }
        }
        CP_COMMIT();

        // compute stage t
        const uint32_t st = sb + (t % STAGES) * STG_SIZE;
#pragma unroll
        for (int ks = 0; ks < 2; ks++) {
            const uint32_t ko = ks * 32;   // 16 bf16 = 32B along K
            uint32_t ah[2][4], al[2][4];
#pragma unroll
            for (int mt = 0; mt < 2; mt++) {
                LDSM4(ah[mt][0], ah[mt][1], ah[mt][2], ah[mt][3], st + STG_A_HI + offA[mt] + ko);
                LDSM4(al[mt][0], al[mt][1], al[mt][2], al[mt][3], st + STG_A_LO + offA[mt] + ko);
            }
#pragma unroll
            for (int pr = 0; pr < 4; pr++) {
                uint32_t bh[4], bl[4];
                LDSM4(bh[0], bh[1], bh[2], bh[3], st + STG_B_HI + offB[pr] + ko);
                LDSM4(bl[0], bl[1], bl[2], bl[3], st + STG_B_LO + offB[pr] + ko);
#pragma unroll
                for (int sub = 0; sub < 2; sub++) {
                    const int nt = pr * 2 + sub;
#pragma unroll
                    for (int mt = 0; mt < 2; mt++) {
                        MMA_BF16(acc[mt][nt], ah[mt], bh[2 * sub], bh[2 * sub + 1]);
                        MMA_BF16(acc[mt][nt], ah[mt], bl[2 * sub], bl[2 * sub + 1]);
                        MMA_BF16(acc[mt][nt], al[mt], bh[2 * sub], bh[2 * sub + 1]);
                    }
                }
            }
        }
    }

    // -------- epilogue: bias add + store --------
    const int ln4 = lane >> 2;
    const int lq  = lane & 3;
#pragma unroll
    for (int mt = 0; mt < 2; mt++) {
#pragma unroll
        for (int nt = 0; nt < 8; nt++) {
            const int m0 = bm + warp_m * 32 + mt * 16 + ln4;
            const int n  = bn + warp_n * 64 + nt * 8 + lq * 2;
            const float2 bv = *(const float2*)(bias + n);
            float2 o0, o1;
            o0.x = acc[mt][nt][0] + bv.x; o0.y = acc[mt][nt][1] + bv.y;
            o1.x = acc[mt][nt][2] + bv.x; o1.y = acc[mt][nt][3] + bv.y;
            *(float2*)(Z + (size_t)m0 * Ndim + n)       = o0;
            *(float2*)(Z + (size_t)(m0 + 8) * Ndim + n) = o1;
        }
    }
}

// ---------------------------------------------------------------------------
// Kernel 2: per-row GroupNorm(4 groups of 2048) + LSTM gates
// z row staged in smem: read z from DRAM once instead of twice.
// ---------------------------------------------------------------------------
__device__ __forceinline__ float sigmoidf_(float x) {
    return 1.f / (1.f + expf(-x));
}

__global__ __launch_bounds__(256) void gn_gates_kernel(
    const float* __restrict__ z, const float* __restrict__ cin,
    const float* __restrict__ gw, const float* __restrict__ gb,
    float* __restrict__ out)
{
    __shared__ float4 zs[2048];          // full z row (32 KB)
    __shared__ float red_s[256], red_q[256];
    __shared__ float s_mean[4], s_rstd[4];

    const int r = blockIdx.x;
    const int t = threadIdx.x;
    const float4* z4 = (const float4*)(z + (size_t)r * Ndim);

    const int g    = t >> 6;
    const int lane = t & 63;
    float s = 0.f, ss = 0.f;
#pragma unroll
    for (int i = 0; i < 8; i++) {
        const int idx = g * 512 + lane + i * 64;
        float4 v = z4[idx];
        zs[idx] = v;
        s  += v.x + v.y + v.z + v.w;
        ss += v.x * v.x + v.y * v.y + v.z * v.z + v.w * v.w;
    }
    red_s[t] = s; red_q[t] = ss;
    __syncthreads();
#pragma unroll
    for (int off = 32; off >= 1; off >>= 1) {
        if (lane < off) {
            red_s[t] += red_s[t + off];
            red_q[t] += red_q[t + off];
        }
        __syncthreads();
    }
    if (t < 4) {
        float m = red_s[t * 64] * (1.f / 2048.f);
        float v = red_q[t * 64] * (1.f / 2048.f) - m * m;
        s_mean[t] = m;
        s_rstd[t] = rsqrtf(v + 1e-5f);
    }
    __syncthreads();

    const float mi = s_mean[0], ri = s_rstd[0];
    const float mf = s_mean[1], rf = s_rstd[1];
    const float mo = s_mean[2], ro = s_rstd[2];
    const float mg = s_mean[3], rg = s_rstd[3];

    const float4* c4  = (const float4*)(cin + (size_t)r * Hdim);
    const float4* gw4 = (const float4*)gw;
    const float4* gb4 = (const float4*)gb;
    float4* h4  = (float4*)out + (size_t)r * (Hdim / 4);
    float4* cn4 = (float4*)out + (size_t)Bdim * (Hdim / 4) + (size_t)r * (Hdim / 4);

#pragma unroll
    for (int p = 0; p < 2; p++) {
        const int j4 = t + p * 256;
        float4 zi = zs[j4];
        float4 zf = zs[512 + j4];
        float4 zo = zs[1024 + j4];
        float4 zg = zs[1536 + j4];
        float4 wi = gw4[j4],        bi  = gb4[j4];
        float4 wf = gw4[512 + j4],  bf2 = gb4[512 + j4];
        float4 wo = gw4[1024 + j4], bo  = gb4[1024 + j4];
        float4 wg = gw4[1536 + j4], bg  = gb4[1536 + j4];
        float4 cv = c4[j4];

        float4 hn, cn;
#define GATE(comp)                                                            \
        {                                                                     \
            float vi = (zi.comp - mi) * ri * wi.comp + bi.comp;               \
            float vf = (zf.comp - mf) * rf * wf.comp + bf2.comp;              \
            float vo = (zo.comp - mo) * ro * wo.comp + bo.comp;               \
            float vg = (zg.comp - mg) * rg * wg.comp + bg.comp;               \
            float cnew = sigmoidf_(vf) * cv.comp + sigmoidf_(vi) * tanhf(vg); \
            cn.comp = cnew;                                                   \
            hn.comp = sigmoidf_(vo) * tanhf(cnew);                            \
        }
        GATE(x); GATE(y); GATE(z); GATE(w);
#undef GATE
        h4[j4]  = hn;
        cn4[j4] = cn;
    }
}

// ---------------------------------------------------------------------------
extern "C" void kernel_launch(void* const* d_in, const int* in_sizes, int n_in,
                              void* d_out, int out_size)
{
    // metadata order: x(0, unused), h(1), c(2), W(3), b(4), gn_weight(5), gn_bias(6)
    const float* h  = (const float*)d_in[1];
    const float* c  = (const float*)d_in[2];
    const float* W  = (const float*)d_in[3];
    const float* b  = (const float*)d_in[4];
    const float* gw = (const float*)d_in[5];
    const float* gb = (const float*)d_in[6];
    float* out = (float*)d_out;

    float* z;            cudaGetSymbolAddress((void**)&z,   g_z);
    __nv_bfloat16 *Ahi, *Alo, *Bhi, *Blo;
    cudaGetSymbolAddress((void**)&Ahi, g_Ahi);
    cudaGetSymbolAddress((void**)&Alo, g_Alo);
    cudaGetSymbolAddress((void**)&Bhi, g_Bhi);
    cudaGetSymbolAddress((void**)&Blo, g_Blo);

    cudaFuncSetAttribute(gemm_tc_kernel,
                         cudaFuncAttributeMaxDynamicSharedMemorySize, SMEM_TOTAL);

    const int nA4 = Bdim * Kdim / 4;
    const int nB4 = Ndim * Kdim / 4;
    split_bf16_kernel<<<(nA4 + 255) / 256, 256>>>(h, Ahi, Alo, nA4);
    split_bf16_kernel<<<(nB4 + 255) / 256, 256>>>(W, Bhi, Blo, nB4);

    dim3 ggrid(Ndim / BN, Bdim / BM);   // (32, 32)
    gemm_tc_kernel<<<ggrid, 512, SMEM_TOTAL>>>(Ahi, Alo, Bhi, Blo, b, z);

    gn_gates_kernel<<<Bdim, 256>>>(z, c, gw, gb, out);
}

// round 5
// speedup vs baseline: 3.3302x; 1.4099x over previous
#include <cuda_runtime.h>
#include <cuda_fp16.h>
#include <math.h>
#include <stdint.h>

// ---------------------------------------------------------------------------
// Problem dims
#define Bdim 4096
#define Hdim 2048
#define Ndim 8192   // 4*H
#define Kdim 2048

// GEMM tiling
#define BM 128
#define BN 256
#define BK 32
#define STAGES 4
#define NT (Kdim / BK)      // 64

// SMEM stage layout (rows of 40 fp16 = 80B; pad 32->40 for conflict-free ldmatrix)
#define RSB  80
#define STG_A_HI 0
#define STG_A_LO 10240
#define STG_B_HI 20480
#define STG_SIZE 40960
#define SMEM_TOTAL (STAGES * STG_SIZE)   // 163840

// Scratch (static device arrays; no runtime allocation allowed)
__device__ float  g_z  [(size_t)Bdim * Ndim];
__device__ __half g_Ahi[(size_t)Bdim * Kdim];
__device__ __half g_Alo[(size_t)Bdim * Kdim];
__device__ __half g_Bhi[(size_t)Ndim * Kdim];

// ---------------------------------------------------------------------------
__device__ __forceinline__ uint32_t smem_u32(const void* p) {
    uint32_t a;
    asm("{ .reg .u64 t; cvta.to.shared.u64 t, %1; cvt.u32.u64 %0, t; }" : "=r"(a) : "l"(p));
    return a;
}
__device__ __forceinline__ void cp16(uint32_t dst, const void* src) {
    asm volatile("cp.async.cg.shared.global [%0], [%1], 16;\n" :: "r"(dst), "l"(src) : "memory");
}
#define CP_COMMIT()  asm volatile("cp.async.commit_group;" ::: "memory")
#define CP_WAIT(n)   asm volatile("cp.async.wait_group %0;" :: "n"(n) : "memory")

#define LDSM4(r0, r1, r2, r3, addr)                                           \
    asm volatile("ldmatrix.sync.aligned.m8n8.x4.shared.b16 {%0,%1,%2,%3},[%4];" \
        : "=r"(r0), "=r"(r1), "=r"(r2), "=r"(r3) : "r"(addr))

#define MMA_F16(d, a, b0, b1)                                                 \
    asm volatile("mma.sync.aligned.m16n8k16.row.col.f32.f16.f16.f32 "         \
        "{%0,%1,%2,%3},{%4,%5,%6,%7},{%8,%9},{%0,%1,%2,%3};"                  \
        : "+f"((d)[0]), "+f"((d)[1]), "+f"((d)[2]), "+f"((d)[3])              \
        : "r"((a)[0]), "r"((a)[1]), "r"((a)[2]), "r"((a)[3]),                 \
          "r"(b0), "r"(b1))

// ---------------------------------------------------------------------------
// Kernel 0a: split fp32 -> (fp16 hi, fp16 lo)     (for A = h)
// ---------------------------------------------------------------------------
__global__ __launch_bounds__(256) void split_fp16_kernel(
    const float* __restrict__ x, __half* __restrict__ hi,
    __half* __restrict__ lo, int n4)
{
    int i = blockIdx.x * blockDim.x + threadIdx.x;
    if (i >= n4) return;
    float4 v = ((const float4*)x)[i];
    __half2 h01, h23, l01, l23;
    __half t;
    t = __float2half_rn(v.x); h01.x = t; l01.x = __float2half_rn(v.x - __half2float(t));
    t = __float2half_rn(v.y); h01.y = t; l01.y = __float2half_rn(v.y - __half2float(t));
    t = __float2half_rn(v.z); h23.x = t; l23.x = __float2half_rn(v.z - __half2float(t));
    t = __float2half_rn(v.w); h23.y = t; l23.y = __float2half_rn(v.w - __half2float(t));
    ((__half2*)hi)[2 * i]     = h01;
    ((__half2*)hi)[2 * i + 1] = h23;
    ((__half2*)lo)[2 * i]     = l01;
    ((__half2*)lo)[2 * i + 1] = l23;
}

// ---------------------------------------------------------------------------
// Kernel 0b: convert fp32 -> fp16                 (for B = W)
// ---------------------------------------------------------------------------
__global__ __launch_bounds__(256) void cvt_fp16_kernel(
    const float* __restrict__ x, __half* __restrict__ y, int n4)
{
    int i = blockIdx.x * blockDim.x + threadIdx.x;
    if (i >= n4) return;
    float4 v = ((const float4*)x)[i];
    __half2 a, b;
    a.x = __float2half_rn(v.x); a.y = __float2half_rn(v.y);
    b.x = __float2half_rn(v.z); b.y = __float2half_rn(v.w);
    ((__half2*)y)[2 * i]     = a;
    ((__half2*)y)[2 * i + 1] = b;
}

// ---------------------------------------------------------------------------
// Kernel 1: z[M,N] = (Ahi+Alo)[M,K] @ Bhi[N,K]^T + bias
// fp16 mma.sync m16n8k16, fp32 accum; 2 MMAs per tile product.
// 256 threads = 8 warps in 2(M) x 4(N); per warp 64x64 (acc = 128 regs).
// ---------------------------------------------------------------------------
__global__ __launch_bounds__(256, 1) void gemm_tc_kernel(
    const __half* __restrict__ Ahi, const __half* __restrict__ Alo,
    const __half* __restrict__ Bhi,
    const float* __restrict__ bias, float* __restrict__ Z)
{
    extern __shared__ char smem[];
    const uint32_t sb = smem_u32(smem);

    const int tid    = threadIdx.x;
    const int lane   = tid & 31;
    const int wid    = tid >> 5;
    const int warp_m = wid & 1;     // 0..1 -> 64 rows each
    const int warp_n = wid >> 1;    // 0..3 -> 64 cols each
    const int bm     = blockIdx.y * BM;
    const int bn     = blockIdx.x * BN;

    const char* Agh = (const char*)(Ahi + (size_t)bm * Kdim);
    const char* Agl = (const char*)(Alo + (size_t)bm * Kdim);
    const char* Bgh = (const char*)(Bhi + (size_t)bn * Kdim);

    // cp.async mapping: 256 threads, 4x16B per 64B row -> 64 rows/pass
    const int lc = (tid & 3) * 16;
    const int lr = tid >> 2;        // 0..63

    // ldmatrix per-lane byte offsets within a stage
    uint32_t offA[4];
#pragma unroll
    for (int mt = 0; mt < 4; mt++)
        offA[mt] = (uint32_t)((warp_m * 64 + mt * 16 + (lane & 15)) * RSB + (lane >> 4) * 16);
    uint32_t offB[4];
#pragma unroll
    for (int pr = 0; pr < 4; pr++)
        offB[pr] = (uint32_t)((warp_n * 64 + pr * 16 + (lane & 7) + ((lane >> 4) & 1) * 8) * RSB
                              + ((lane >> 3) & 1) * 16);

    float acc[4][8][4];
#pragma unroll
    for (int mt = 0; mt < 4; mt++)
#pragma unroll
        for (int nt = 0; nt < 8; nt++)
#pragma unroll
            for (int q = 0; q < 4; q++) acc[mt][nt][q] = 0.f;

    // -------- pipeline prologue: load stages 0..STAGES-2 --------
#pragma unroll
    for (int t = 0; t < STAGES - 1; t++) {
        const uint32_t st = sb + t * STG_SIZE;
        const size_t kb = (size_t)t * (BK * 2);
#pragma unroll
        for (int p = 0; p < 2; p++) {       // A: 128 rows
            const int r = lr + p * 64;
            const size_t go = (size_t)r * (Kdim * 2) + kb + lc;
            const uint32_t so = r * RSB + lc;
            cp16(st + STG_A_HI + so, Agh + go);
            cp16(st + STG_A_LO + so, Agl + go);
        }
#pragma unroll
        for (int p = 0; p < 4; p++) {       // B: 256 rows (hi only)
            const int r = lr + p * 64;
            const size_t go = (size_t)r * (Kdim * 2) + kb + lc;
            cp16(st + STG_B_HI + r * RSB + lc, Bgh + go);
        }
        CP_COMMIT();
    }

    // -------- main loop --------
    for (int t = 0; t < NT; t++) {
        CP_WAIT(STAGES - 2);
        __syncthreads();

        const int tn = t + STAGES - 1;
        if (tn < NT) {
            const uint32_t st = sb + (tn % STAGES) * STG_SIZE;
            const size_t kb = (size_t)tn * (BK * 2);
#pragma unroll
            for (int p = 0; p < 2; p++) {
                const int r = lr + p * 64;
                const size_t go = (size_t)r * (Kdim * 2) + kb + lc;
                const uint32_t so = r * RSB + lc;
                cp16(st + STG_A_HI + so, Agh + go);
                cp16(st + STG_A_LO + so, Agl + go);
            }
#pragma unroll
            for (int p = 0; p < 4; p++) {
                const int r = lr + p * 64;
                const size_t go = (size_t)r * (Kdim * 2) + kb + lc;
                cp16(st + STG_B_HI + r * RSB + lc, Bgh + go);
            }
        }
        CP_COMMIT();

        // compute stage t
        const uint32_t st = sb + (t % STAGES) * STG_SIZE;
#pragma unroll
        for (int ks = 0; ks < 2; ks++) {
            const uint32_t ko = ks * 32;   // 16 fp16 = 32B along K
            uint32_t ah[4][4], al[4][4];
#pragma unroll
            for (int mt = 0; mt < 4; mt++) {
                LDSM4(ah[mt][0], ah[mt][1], ah[mt][2], ah[mt][3], st + STG_A_HI + offA[mt] + ko);
                LDSM4(al[mt][0], al[mt][1], al[mt][2], al[mt][3], st + STG_A_LO + offA[mt] + ko);
            }
#pragma unroll
            for (int pr = 0; pr < 4; pr++) {
                uint32_t bh[4];
                LDSM4(bh[0], bh[1], bh[2], bh[3], st + STG_B_HI + offB[pr] + ko);
#pragma unroll
                for (int sub = 0; sub < 2; sub++) {
                    const int nt = pr * 2 + sub;
#pragma unroll
                    for (int mt = 0; mt < 4; mt++) {
                        MMA_F16(acc[mt][nt], ah[mt], bh[2 * sub], bh[2 * sub + 1]);
                        MMA_F16(acc[mt][nt], al[mt], bh[2 * sub], bh[2 * sub + 1]);
                    }
                }
            }
        }
    }

    // -------- epilogue: bias add + store --------
    const int ln4 = lane >> 2;
    const int lq  = lane & 3;
#pragma unroll
    for (int mt = 0; mt < 4; mt++) {
#pragma unroll
        for (int nt = 0; nt < 8; nt++) {
            const int m0 = bm + warp_m * 64 + mt * 16 + ln4;
            const int n  = bn + warp_n * 64 + nt * 8 + lq * 2;
            const float2 bv = *(const float2*)(bias + n);
            float2 o0, o1;
            o0.x = acc[mt][nt][0] + bv.x; o0.y = acc[mt][nt][1] + bv.y;
            o1.x = acc[mt][nt][2] + bv.x; o1.y = acc[mt][nt][3] + bv.y;
            *(float2*)(Z + (size_t)m0 * Ndim + n)       = o0;
            *(float2*)(Z + (size_t)(m0 + 8) * Ndim + n) = o1;
        }
    }
}

// ---------------------------------------------------------------------------
// Kernel 2: per-row GroupNorm(4 groups of 2048) + LSTM gates
// ---------------------------------------------------------------------------
__device__ __forceinline__ float sigmoidf_(float x) {
    return 1.f / (1.f + expf(-x));
}

__global__ __launch_bounds__(256) void gn_gates_kernel(
    const float* __restrict__ z, const float* __restrict__ cin,
    const float* __restrict__ gw, const float* __restrict__ gb,
    float* __restrict__ out)
{
    __shared__ float4 zs[2048];          // full z row (32 KB)
    __shared__ float red_s[256], red_q[256];
    __shared__ float s_mean[4], s_rstd[4];

    const int r = blockIdx.x;
    const int t = threadIdx.x;
    const float4* z4 = (const float4*)(z + (size_t)r * Ndim);

    const int g    = t >> 6;
    const int lane = t & 63;
    float s = 0.f, ss = 0.f;
#pragma unroll
    for (int i = 0; i < 8; i++) {
        const int idx = g * 512 + lane + i * 64;
        float4 v = z4[idx];
        zs[idx] = v;
        s  += v.x + v.y + v.z + v.w;
        ss += v.x * v.x + v.y * v.y + v.z * v.z + v.w * v.w;
    }
    red_s[t] = s; red_q[t] = ss;
    __syncthreads();
#pragma unroll
    for (int off = 32; off >= 1; off >>= 1) {
        if (lane < off) {
            red_s[t] += red_s[t + off];
            red_q[t] += red_q[t + off];
        }
        __syncthreads();
    }
    if (t < 4) {
        float m = red_s[t * 64] * (1.f / 2048.f);
        float v = red_q[t * 64] * (1.f / 2048.f) - m * m;
        s_mean[t] = m;
        s_rstd[t] = rsqrtf(v + 1e-5f);
    }
    __syncthreads();

    const float mi = s_mean[0], ri = s_rstd[0];
    const float mf = s_mean[1], rf = s_rstd[1];
    const float mo = s_mean[2], ro = s_rstd[2];
    const float mg = s_mean[3], rg = s_rstd[3];

    const float4* c4  = (const float4*)(cin + (size_t)r * Hdim);
    const float4* gw4 = (const float4*)gw;
    const float4* gb4 = (const float4*)gb;
    float4* h4  = (float4*)out + (size_t)r * (Hdim / 4);
    float4* cn4 = (float4*)out + (size_t)Bdim * (Hdim / 4) + (size_t)r * (Hdim / 4);

#pragma unroll
    for (int p = 0; p < 2; p++) {
        const int j4 = t + p * 256;
        float4 zi = zs[j4];
        float4 zf = zs[512 + j4];
        float4 zo = zs[1024 + j4];
        float4 zg = zs[1536 + j4];
        float4 wi = gw4[j4],        bi  = gb4[j4];
        float4 wf = gw4[512 + j4],  bf2 = gb4[512 + j4];
        float4 wo = gw4[1024 + j4], bo  = gb4[1024 + j4];
        float4 wg = gw4[1536 + j4], bg  = gb4[1536 + j4];
        float4 cv = c4[j4];

        float4 hn, cn;
#define GATE(comp)                                                            \
        {                                                                     \
            float vi = (zi.comp - mi) * ri * wi.comp + bi.comp;               \
            float vf = (zf.comp - mf) * rf * wf.comp + bf2.comp;              \
            float vo = (zo.comp - mo) * ro * wo.comp + bo.comp;               \
            float vg = (zg.comp - mg) * rg * wg.comp + bg.comp;               \
            float cnew = sigmoidf_(vf) * cv.comp + sigmoidf_(vi) * tanhf(vg); \
            cn.comp = cnew;                                                   \
            hn.comp = sigmoidf_(vo) * tanhf(cnew);                            \
        }
        GATE(x); GATE(y); GATE(z); GATE(w);
#undef GATE
        h4[j4]  = hn;
        cn4[j4] = cn;
    }
}

// ---------------------------------------------------------------------------
extern "C" void kernel_launch(void* const* d_in, const int* in_sizes, int n_in,
                              void* d_out, int out_size)
{
    // metadata order: x(0, unused), h(1), c(2), W(3), b(4), gn_weight(5), gn_bias(6)
    const float* h  = (const float*)d_in[1];
    const float* c  = (const float*)d_in[2];
    const float* W  = (const float*)d_in[3];
    const float* b  = (const float*)d_in[4];
    const float* gw = (const float*)d_in[5];
    const float* gb = (const float*)d_in[6];
    float* out = (float*)d_out;

    float* z;          cudaGetSymbolAddress((void**)&z, g_z);
    __half *Ahi, *Alo, *Bhi;
    cudaGetSymbolAddress((void**)&Ahi, g_Ahi);
    cudaGetSymbolAddress((void**)&Alo, g_Alo);
    cudaGetSymbolAddress((void**)&Bhi, g_Bhi);

    cudaFuncSetAttribute(gemm_tc_kernel,
                         cudaFuncAttributeMaxDynamicSharedMemorySize, SMEM_TOTAL);

    const int nA4 = Bdim * Kdim / 4;
    const int nB4 = Ndim * Kdim / 4;
    split_fp16_kernel<<<(nA4 + 255) / 256, 256>>>(h, Ahi, Alo, nA4);
    cvt_fp16_kernel<<<(nB4 + 255) / 256, 256>>>(W, Bhi, nB4);

    dim3 ggrid(Ndim / BN, Bdim / BM);   // (32, 32)
    gemm_tc_kernel<<<ggrid, 256, SMEM_TOTAL>>>(Ahi, Alo, Bhi, b, z);

    gn_gates_kernel<<<Bdim, 256>>>(z, c, gw, gb, out);
}

// round 6
// speedup vs baseline: 4.8854x; 1.4670x over previous
#include <cuda_runtime.h>
#include <cuda_fp16.h>
#include <math.h>
#include <stdint.h>

// ---------------------------------------------------------------------------
// Problem dims
#define Bdim 4096
#define Hdim 2048
#define Ndim 8192   // 4*H
#define Kdim 2048

// GEMM tiling
#define BM 128
#define BN 256
#define BK 32
#define STAGES 5
#define NT (Kdim / BK)      // 64

// SMEM stage layout (rows of 40 fp16 = 80B; pad 32->40 for conflict-free ldmatrix)
#define RSB  80
#define STG_A 0
#define STG_B 10240
#define STG_SIZE 30720
#define SMEM_TOTAL (STAGES * STG_SIZE)   // 153600

// Scratch (static device arrays; no runtime allocation allowed)
__device__ float  g_z [(size_t)Bdim * Ndim];
__device__ __half g_Ah[(size_t)Bdim * Kdim];
__device__ __half g_Bh[(size_t)Ndim * Kdim];

// ---------------------------------------------------------------------------
__device__ __forceinline__ uint32_t smem_u32(const void* p) {
    uint32_t a;
    asm("{ .reg .u64 t; cvta.to.shared.u64 t, %1; cvt.u32.u64 %0, t; }" : "=r"(a) : "l"(p));
    return a;
}
__device__ __forceinline__ void cp16(uint32_t dst, const void* src) {
    asm volatile("cp.async.cg.shared.global [%0], [%1], 16;\n" :: "r"(dst), "l"(src) : "memory");
}
#define CP_COMMIT()  asm volatile("cp.async.commit_group;" ::: "memory")
#define CP_WAIT(n)   asm volatile("cp.async.wait_group %0;" :: "n"(n) : "memory")

#define LDSM4(r0, r1, r2, r3, addr)                                           \
    asm volatile("ldmatrix.sync.aligned.m8n8.x4.shared.b16 {%0,%1,%2,%3},[%4];" \
        : "=r"(r0), "=r"(r1), "=r"(r2), "=r"(r3) : "r"(addr))

#define MMA_F16(d, a, b0, b1)                                                 \
    asm volatile("mma.sync.aligned.m16n8k16.row.col.f32.f16.f16.f32 "         \
        "{%0,%1,%2,%3},{%4,%5,%6,%7},{%8,%9},{%0,%1,%2,%3};"                  \
        : "+f"((d)[0]), "+f"((d)[1]), "+f"((d)[2]), "+f"((d)[3])              \
        : "r"((a)[0]), "r"((a)[1]), "r"((a)[2]), "r"((a)[3]),                 \
          "r"(b0), "r"(b1))

// ---------------------------------------------------------------------------
// Kernel 0: convert fp32 -> fp16
// ---------------------------------------------------------------------------
__global__ __launch_bounds__(256) void cvt_fp16_kernel(
    const float* __restrict__ x, __half* __restrict__ y, int n4)
{
    int i = blockIdx.x * blockDim.x + threadIdx.x;
    if (i >= n4) return;
    float4 v = ((const float4*)x)[i];
    __half2 a, b;
    a.x = __float2half_rn(v.x); a.y = __float2half_rn(v.y);
    b.x = __float2half_rn(v.z); b.y = __float2half_rn(v.w);
    ((__half2*)y)[2 * i]     = a;
    ((__half2*)y)[2 * i + 1] = b;
}

// ---------------------------------------------------------------------------
// Kernel 1: z[M,N] = A[M,K] @ B[N,K]^T + bias   (fp16 inputs, fp32 accum)
// 256 threads = 8 warps in 2(M) x 4(N); per warp 64x64 (acc = 128 regs).
// ---------------------------------------------------------------------------
__global__ __launch_bounds__(256, 1) void gemm_tc_kernel(
    const __half* __restrict__ A, const __half* __restrict__ B,
    const float* __restrict__ bias, float* __restrict__ Z)
{
    extern __shared__ char smem[];
    const uint32_t sb = smem_u32(smem);

    const int tid    = threadIdx.x;
    const int lane   = tid & 31;
    const int wid    = tid >> 5;
    const int warp_m = wid & 1;     // 0..1 -> 64 rows each
    const int warp_n = wid >> 1;    // 0..3 -> 64 cols each
    const int bm     = blockIdx.y * BM;
    const int bn     = blockIdx.x * BN;

    const char* Ag = (const char*)(A + (size_t)bm * Kdim);
    const char* Bg = (const char*)(B + (size_t)bn * Kdim);

    // cp.async mapping: 256 threads, 4x16B per 64B row -> 64 rows/pass
    const int lc = (tid & 3) * 16;
    const int lr = tid >> 2;        // 0..63

    // ldmatrix per-lane byte offsets within a stage
    uint32_t offA[4];
#pragma unroll
    for (int mt = 0; mt < 4; mt++)
        offA[mt] = (uint32_t)((warp_m * 64 + mt * 16 + (lane & 15)) * RSB + (lane >> 4) * 16);
    uint32_t offB[4];
#pragma unroll
    for (int pr = 0; pr < 4; pr++)
        offB[pr] = (uint32_t)((warp_n * 64 + pr * 16 + (lane & 7) + ((lane >> 4) & 1) * 8) * RSB
                              + ((lane >> 3) & 1) * 16);

    float acc[4][8][4];
#pragma unroll
    for (int mt = 0; mt < 4; mt++)
#pragma unroll
        for (int nt = 0; nt < 8; nt++)
#pragma unroll
            for (int q = 0; q < 4; q++) acc[mt][nt][q] = 0.f;

    // -------- pipeline prologue: load stages 0..STAGES-2 --------
#pragma unroll
    for (int t = 0; t < STAGES - 1; t++) {
        const uint32_t st = sb + t * STG_SIZE;
        const size_t kb = (size_t)t * (BK * 2);
#pragma unroll
        for (int p = 0; p < 2; p++) {       // A: 128 rows
            const int r = lr + p * 64;
            cp16(st + STG_A + r * RSB + lc, Ag + (size_t)r * (Kdim * 2) + kb + lc);
        }
#pragma unroll
        for (int p = 0; p < 4; p++) {       // B: 256 rows
            const int r = lr + p * 64;
            cp16(st + STG_B + r * RSB + lc, Bg + (size_t)r * (Kdim * 2) + kb + lc);
        }
        CP_COMMIT();
    }

    // -------- main loop --------
    for (int t = 0; t < NT; t++) {
        CP_WAIT(STAGES - 2);
        __syncthreads();

        const int tn = t + STAGES - 1;
        if (tn < NT) {
            const uint32_t st = sb + (tn % STAGES) * STG_SIZE;
            const size_t kb = (size_t)tn * (BK * 2);
#pragma unroll
            for (int p = 0; p < 2; p++) {
                const int r = lr + p * 64;
                cp16(st + STG_A + r * RSB + lc, Ag + (size_t)r * (Kdim * 2) + kb + lc);
            }
#pragma unroll
            for (int p = 0; p < 4; p++) {
                const int r = lr + p * 64;
                cp16(st + STG_B + r * RSB + lc, Bg + (size_t)r * (Kdim * 2) + kb + lc);
            }
        }
        CP_COMMIT();

        // compute stage t
        const uint32_t st = sb + (t % STAGES) * STG_SIZE;
#pragma unroll
        for (int ks = 0; ks < 2; ks++) {
            const uint32_t ko = ks * 32;   // 16 fp16 = 32B along K
            uint32_t ah[4][4];
#pragma unroll
            for (int mt = 0; mt < 4; mt++)
                LDSM4(ah[mt][0], ah[mt][1], ah[mt][2], ah[mt][3], st + STG_A + offA[mt] + ko);
#pragma unroll
            for (int pr = 0; pr < 4; pr++) {
                uint32_t bh[4];
                LDSM4(bh[0], bh[1], bh[2], bh[3], st + STG_B + offB[pr] + ko);
#pragma unroll
                for (int sub = 0; sub < 2; sub++) {
                    const int nt = pr * 2 + sub;
#pragma unroll
                    for (int mt = 0; mt < 4; mt++)
                        MMA_F16(acc[mt][nt], ah[mt], bh[2 * sub], bh[2 * sub + 1]);
                }
            }
        }
    }

    // -------- epilogue: bias add + store --------
    const int ln4 = lane >> 2;
    const int lq  = lane & 3;
#pragma unroll
    for (int mt = 0; mt < 4; mt++) {
#pragma unroll
        for (int nt = 0; nt < 8; nt++) {
            const int m0 = bm + warp_m * 64 + mt * 16 + ln4;
            const int n  = bn + warp_n * 64 + nt * 8 + lq * 2;
            const float2 bv = *(const float2*)(bias + n);
            float2 o0, o1;
            o0.x = acc[mt][nt][0] + bv.x; o0.y = acc[mt][nt][1] + bv.y;
            o1.x = acc[mt][nt][2] + bv.x; o1.y = acc[mt][nt][3] + bv.y;
            *(float2*)(Z + (size_t)m0 * Ndim + n)       = o0;
            *(float2*)(Z + (size_t)(m0 + 8) * Ndim + n) = o1;
        }
    }
}

// ---------------------------------------------------------------------------
// Kernel 2: per-row GroupNorm(4 groups of 2048) + LSTM gates
// ---------------------------------------------------------------------------
__device__ __forceinline__ float sigmoidf_(float x) {
    return 1.f / (1.f + expf(-x));
}

__global__ __launch_bounds__(256) void gn_gates_kernel(
    const float* __restrict__ z, const float* __restrict__ cin,
    const float* __restrict__ gw, const float* __restrict__ gb,
    float* __restrict__ out)
{
    __shared__ float4 zs[2048];          // full z row (32 KB)
    __shared__ float red_s[256], red_q[256];
    __shared__ float s_mean[4], s_rstd[4];

    const int r = blockIdx.x;
    const int t = threadIdx.x;
    const float4* z4 = (const float4*)(z + (size_t)r * Ndim);

    const int g    = t >> 6;
    const int lane = t & 63;
    float s = 0.f, ss = 0.f;
#pragma unroll
    for (int i = 0; i < 8; i++) {
        const int idx = g * 512 + lane + i * 64;
        float4 v = z4[idx];
        zs[idx] = v;
        s  += v.x + v.y + v.z + v.w;
        ss += v.x * v.x + v.y * v.y + v.z * v.z + v.w * v.w;
    }
    red_s[t] = s; red_q[t] = ss;
    __syncthreads();
#pragma unroll
    for (int off = 32; off >= 1; off >>= 1) {
        if (lane < off) {
            red_s[t] += red_s[t + off];
            red_q[t] += red_q[t + off];
        }
        __syncthreads();
    }
    if (t < 4) {
        float m = red_s[t * 64] * (1.f / 2048.f);
        float v = red_q[t * 64] * (1.f / 2048.f) - m * m;
        s_mean[t] = m;
        s_rstd[t] = rsqrtf(v + 1e-5f);
    }
    __syncthreads();

    const float mi = s_mean[0], ri = s_rstd[0];
    const float mf = s_mean[1], rf = s_rstd[1];
    const float mo = s_mean[2], ro = s_rstd[2];
    const float mg = s_mean[3], rg = s_rstd[3];

    const float4* c4  = (const float4*)(cin + (size_t)r * Hdim);
    const float4* gw4 = (const float4*)gw;
    const float4* gb4 = (const float4*)gb;
    float4* h4  = (float4*)out + (size_t)r * (Hdim / 4);
    float4* cn4 = (float4*)out + (size_t)Bdim * (Hdim / 4) + (size_t)r * (Hdim / 4);

#pragma unroll
    for (int p = 0; p < 2; p++) {
        const int j4 = t + p * 256;
        float4 zi = zs[j4];
        float4 zf = zs[512 + j4];
        float4 zo = zs[1024 + j4];
        float4 zg = zs[1536 + j4];
        float4 wi = gw4[j4],        bi  = gb4[j4];
        float4 wf = gw4[512 + j4],  bf2 = gb4[512 + j4];
        float4 wo = gw4[1024 + j4], bo  = gb4[1024 + j4];
        float4 wg = gw4[1536 + j4], bg  = gb4[1536 + j4];
        float4 cv = c4[j4];

        float4 hn, cn;
#define GATE(comp)                                                            \
        {                                                                     \
            float vi = (zi.comp - mi) * ri * wi.comp + bi.comp;               \
            float vf = (zf.comp - mf) * rf * wf.comp + bf2.comp;              \
            float vo = (zo.comp - mo) * ro * wo.comp + bo.comp;               \
            float vg = (zg.comp - mg) * rg * wg.comp + bg.comp;               \
            float cnew = sigmoidf_(vf) * cv.comp + sigmoidf_(vi) * tanhf(vg); \
            cn.comp = cnew;                                                   \
            hn.comp = sigmoidf_(vo) * tanhf(cnew);                            \
        }
        GATE(x); GATE(y); GATE(z); GATE(w);
#undef GATE
        h4[j4]  = hn;
        cn4[j4] = cn;
    }
}

// ---------------------------------------------------------------------------
extern "C" void kernel_launch(void* const* d_in, const int* in_sizes, int n_in,
                              void* d_out, int out_size)
{
    // metadata order: x(0, unused), h(1), c(2), W(3), b(4), gn_weight(5), gn_bias(6)
    const float* h  = (const float*)d_in[1];
    const float* c  = (const float*)d_in[2];
    const float* W  = (const float*)d_in[3];
    const float* b  = (const float*)d_in[4];
    const float* gw = (const float*)d_in[5];
    const float* gb = (const float*)d_in[6];
    float* out = (float*)d_out;

    float* z;          cudaGetSymbolAddress((void**)&z, g_z);
    __half *Ah, *Bh;
    cudaGetSymbolAddress((void**)&Ah, g_Ah);
    cudaGetSymbolAddress((void**)&Bh, g_Bh);

    cudaFuncSetAttribute(gemm_tc_kernel,
                         cudaFuncAttributeMaxDynamicSharedMemorySize, SMEM_TOTAL);

    const int nA4 = Bdim * Kdim / 4;
    const int nB4 = Ndim * Kdim / 4;
    cvt_fp16_kernel<<<(nA4 + 255) / 256, 256>>>(h, Ah, nA4);
    cvt_fp16_kernel<<<(nB4 + 255) / 256, 256>>>(W, Bh, nB4);

    dim3 ggrid(Ndim / BN, Bdim / BM);   // (32, 32)
    gemm_tc_kernel<<<ggrid, 256, SMEM_TOTAL>>>(Ah, Bh, b, z);

    gn_gates_kernel<<<Bdim, 256>>>(z, c, gw, gb, out);
}

// round 7
// speedup vs baseline: 5.5942x; 1.1451x over previous
#include <cuda_runtime.h>
#include <cuda_fp16.h>
#include <math.h>
#include <stdint.h>

// ---------------------------------------------------------------------------
// Problem dims
#define Bdim 4096
#define Hdim 2048
#define Ndim 8192   // 4*H
#define Kdim 2048

// GEMM tiling
#define BM 128
#define BN 128
#define BK 32
#define STAGES 4
#define NT (Kdim / BK)      // 64

// SMEM stage layout (rows of 40 fp16 = 80B; pad 32->40 for conflict-free ldmatrix)
#define RSB  80
#define STG_A 0
#define STG_B 10240
#define STG_SIZE 20480
#define SMEM_TOTAL (STAGES * STG_SIZE)   // 81920 per CTA -> 2 CTAs/SM

// Scratch (static device arrays; no runtime allocation allowed)
__device__ float  g_z [(size_t)Bdim * Ndim];
__device__ __half g_Ah[(size_t)Bdim * Kdim];
__device__ __half g_Bh[(size_t)Ndim * Kdim];

// ---------------------------------------------------------------------------
__device__ __forceinline__ uint32_t smem_u32(const void* p) {
    uint32_t a;
    asm("{ .reg .u64 t; cvta.to.shared.u64 t, %1; cvt.u32.u64 %0, t; }" : "=r"(a) : "l"(p));
    return a;
}
__device__ __forceinline__ void cp16(uint32_t dst, const void* src) {
    asm volatile("cp.async.cg.shared.global [%0], [%1], 16;\n" :: "r"(dst), "l"(src) : "memory");
}
#define CP_COMMIT()  asm volatile("cp.async.commit_group;" ::: "memory")
#define CP_WAIT(n)   asm volatile("cp.async.wait_group %0;" :: "n"(n) : "memory")

#define LDSM4(r0, r1, r2, r3, addr)                                           \
    asm volatile("ldmatrix.sync.aligned.m8n8.x4.shared.b16 {%0,%1,%2,%3},[%4];" \
        : "=r"(r0), "=r"(r1), "=r"(r2), "=r"(r3) : "r"(addr))

#define MMA_F16(d, a, b0, b1)                                                 \
    asm volatile("mma.sync.aligned.m16n8k16.row.col.f32.f16.f16.f32 "         \
        "{%0,%1,%2,%3},{%4,%5,%6,%7},{%8,%9},{%0,%1,%2,%3};"                  \
        : "+f"((d)[0]), "+f"((d)[1]), "+f"((d)[2]), "+f"((d)[3])              \
        : "r"((a)[0]), "r"((a)[1]), "r"((a)[2]), "r"((a)[3]),                 \
          "r"(b0), "r"(b1))

// ---------------------------------------------------------------------------
// Kernel 0: convert fp32 -> fp16
// ---------------------------------------------------------------------------
__global__ __launch_bounds__(256) void cvt_fp16_kernel(
    const float* __restrict__ x, __half* __restrict__ y, int n4)
{
    int i = blockIdx.x * blockDim.x + threadIdx.x;
    if (i >= n4) return;
    float4 v = ((const float4*)x)[i];
    __half2 a, b;
    a.x = __float2half_rn(v.x); a.y = __float2half_rn(v.y);
    b.x = __float2half_rn(v.z); b.y = __float2half_rn(v.w);
    ((__half2*)y)[2 * i]     = a;
    ((__half2*)y)[2 * i + 1] = b;
}

// ---------------------------------------------------------------------------
// Kernel 1: z[M,N] = A[M,K] @ B[N,K]^T + bias   (fp16 inputs, fp32 accum)
// 256 threads = 8 warps in 2(M) x 4(N); per warp 64x32 (acc = 64 regs).
// 2 CTAs per SM (4 warps/SMSP) to hide LDSM + sync latency.
// ---------------------------------------------------------------------------
__global__ __launch_bounds__(256, 2) void gemm_tc_kernel(
    const __half* __restrict__ A, const __half* __restrict__ B,
    const float* __restrict__ bias, float* __restrict__ Z)
{
    extern __shared__ char smem[];
    const uint32_t sb = smem_u32(smem);

    const int tid    = threadIdx.x;
    const int lane   = tid & 31;
    const int wid    = tid >> 5;
    const int warp_m = wid & 1;     // 0..1 -> 64 rows each
    const int warp_n = wid >> 1;    // 0..3 -> 32 cols each
    const int bm     = blockIdx.y * BM;
    const int bn     = blockIdx.x * BN;

    const char* Ag = (const char*)(A + (size_t)bm * Kdim);
    const char* Bg = (const char*)(B + (size_t)bn * Kdim);

    // cp.async mapping: 256 threads, 4x16B per 64B row -> 64 rows/pass
    const int lc = (tid & 3) * 16;
    const int lr = tid >> 2;        // 0..63

    // ldmatrix per-lane byte offsets within a stage
    uint32_t offA[4];
#pragma unroll
    for (int mt = 0; mt < 4; mt++)
        offA[mt] = (uint32_t)((warp_m * 64 + mt * 16 + (lane & 15)) * RSB + (lane >> 4) * 16);
    uint32_t offB[2];
#pragma unroll
    for (int pr = 0; pr < 2; pr++)
        offB[pr] = (uint32_t)((warp_n * 32 + pr * 16 + (lane & 7) + ((lane >> 4) & 1) * 8) * RSB
                              + ((lane >> 3) & 1) * 16);

    float acc[4][4][4];
#pragma unroll
    for (int mt = 0; mt < 4; mt++)
#pragma unroll
        for (int nt = 0; nt < 4; nt++)
#pragma unroll
            for (int q = 0; q < 4; q++) acc[mt][nt][q] = 0.f;

    // -------- pipeline prologue: load stages 0..STAGES-2 --------
#pragma unroll
    for (int t = 0; t < STAGES - 1; t++) {
        const uint32_t st = sb + t * STG_SIZE;
        const size_t kb = (size_t)t * (BK * 2);
#pragma unroll
        for (int p = 0; p < 2; p++) {
            const int r = lr + p * 64;
            cp16(st + STG_A + r * RSB + lc, Ag + (size_t)r * (Kdim * 2) + kb + lc);
            cp16(st + STG_B + r * RSB + lc, Bg + (size_t)r * (Kdim * 2) + kb + lc);
        }
        CP_COMMIT();
    }

    // -------- main loop --------
    for (int t = 0; t < NT; t++) {
        CP_WAIT(STAGES - 2);
        __syncthreads();

        const int tn = t + STAGES - 1;
        if (tn < NT) {
            const uint32_t st = sb + (tn % STAGES) * STG_SIZE;
            const size_t kb = (size_t)tn * (BK * 2);
#pragma unroll
            for (int p = 0; p < 2; p++) {
                const int r = lr + p * 64;
                cp16(st + STG_A + r * RSB + lc, Ag + (size_t)r * (Kdim * 2) + kb + lc);
                cp16(st + STG_B + r * RSB + lc, Bg + (size_t)r * (Kdim * 2) + kb + lc);
            }
        }
        CP_COMMIT();

        // compute stage t
        const uint32_t st = sb + (t % STAGES) * STG_SIZE;
#pragma unroll
        for (int ks = 0; ks < 2; ks++) {
            const uint32_t ko = ks * 32;   // 16 fp16 = 32B along K
            uint32_t ah[4][4];
#pragma unroll
            for (int mt = 0; mt < 4; mt++)
                LDSM4(ah[mt][0], ah[mt][1], ah[mt][2], ah[mt][3], st + STG_A + offA[mt] + ko);
#pragma unroll
            for (int pr = 0; pr < 2; pr++) {
                uint32_t bh[4];
                LDSM4(bh[0], bh[1], bh[2], bh[3], st + STG_B + offB[pr] + ko);
#pragma unroll
                for (int sub = 0; sub < 2; sub++) {
                    const int nt = pr * 2 + sub;
#pragma unroll
                    for (int mt = 0; mt < 4; mt++)
                        MMA_F16(acc[mt][nt], ah[mt], bh[2 * sub], bh[2 * sub + 1]);
                }
            }
        }
    }

    // -------- epilogue: bias add + store --------
    const int ln4 = lane >> 2;
    const int lq  = lane & 3;
#pragma unroll
    for (int mt = 0; mt < 4; mt++) {
#pragma unroll
        for (int nt = 0; nt < 4; nt++) {
            const int m0 = bm + warp_m * 64 + mt * 16 + ln4;
            const int n  = bn + warp_n * 32 + nt * 8 + lq * 2;
            const float2 bv = *(const float2*)(bias + n);
            float2 o0, o1;
            o0.x = acc[mt][nt][0] + bv.x; o0.y = acc[mt][nt][1] + bv.y;
            o1.x = acc[mt][nt][2] + bv.x; o1.y = acc[mt][nt][3] + bv.y;
            *(float2*)(Z + (size_t)m0 * Ndim + n)       = o0;
            *(float2*)(Z + (size_t)(m0 + 8) * Ndim + n) = o1;
        }
    }
}

// ---------------------------------------------------------------------------
// Kernel 2: per-row GroupNorm(4 groups of 2048) + LSTM gates
// ---------------------------------------------------------------------------
__device__ __forceinline__ float sigmoidf_(float x) {
    return 1.f / (1.f + expf(-x));
}

__global__ __launch_bounds__(256) void gn_gates_kernel(
    const float* __restrict__ z, const float* __restrict__ cin,
    const float* __restrict__ gw, const float* __restrict__ gb,
    float* __restrict__ out)
{
    __shared__ float4 zs[2048];          // full z row (32 KB)
    __shared__ float red_s[256], red_q[256];
    __shared__ float s_mean[4], s_rstd[4];

    const int r = blockIdx.x;
    const int t = threadIdx.x;
    const float4* z4 = (const float4*)(z + (size_t)r * Ndim);

    const int g    = t >> 6;
    const int lane = t & 63;
    float s = 0.f, ss = 0.f;
#pragma unroll
    for (int i = 0; i < 8; i++) {
        const int idx = g * 512 + lane + i * 64;
        float4 v = z4[idx];
        zs[idx] = v;
        s  += v.x + v.y + v.z + v.w;
        ss += v.x * v.x + v.y * v.y + v.z * v.z + v.w * v.w;
    }
    red_s[t] = s; red_q[t] = ss;
    __syncthreads();
#pragma unroll
    for (int off = 32; off >= 1; off >>= 1) {
        if (lane < off) {
            red_s[t] += red_s[t + off];
            red_q[t] += red_q[t + off];
        }
        __syncthreads();
    }
    if (t < 4) {
        float m = red_s[t * 64] * (1.f / 2048.f);
        float v = red_q[t * 64] * (1.f / 2048.f) - m * m;
        s_mean[t] = m;
        s_rstd[t] = rsqrtf(v + 1e-5f);
    }
    __syncthreads();

    const float mi = s_mean[0], ri = s_rstd[0];
    const float mf = s_mean[1], rf = s_rstd[1];
    const float mo = s_mean[2], ro = s_rstd[2];
    const float mg = s_mean[3], rg = s_rstd[3];

    const float4* c4  = (const float4*)(cin + (size_t)r * Hdim);
    const float4* gw4 = (const float4*)gw;
    const float4* gb4 = (const float4*)gb;
    float4* h4  = (float4*)out + (size_t)r * (Hdim / 4);
    float4* cn4 = (float4*)out + (size_t)Bdim * (Hdim / 4) + (size_t)r * (Hdim / 4);

#pragma unroll
    for (int p = 0; p < 2; p++) {
        const int j4 = t + p * 256;
        float4 zi = zs[j4];
        float4 zf = zs[512 + j4];
        float4 zo = zs[1024 + j4];
        float4 zg = zs[1536 + j4];
        float4 wi = gw4[j4],        bi  = gb4[j4];
        float4 wf = gw4[512 + j4],  bf2 = gb4[512 + j4];
        float4 wo = gw4[1024 + j4], bo  = gb4[1024 + j4];
        float4 wg = gw4[1536 + j4], bg  = gb4[1536 + j4];
        float4 cv = c4[j4];

        float4 hn, cn;
#define GATE(comp)                                                            \
        {                                                                     \
            float vi = (zi.comp - mi) * ri * wi.comp + bi.comp;               \
            float vf = (zf.comp - mf) * rf * wf.comp + bf2.comp;              \
            float vo = (zo.comp - mo) * ro * wo.comp + bo.comp;               \
            float vg = (zg.comp - mg) * rg * wg.comp + bg.comp;               \
            float cnew = sigmoidf_(vf) * cv.comp + sigmoidf_(vi) * tanhf(vg); \
            cn.comp = cnew;                                                   \
            hn.comp = sigmoidf_(vo) * tanhf(cnew);                            \
        }
        GATE(x); GATE(y); GATE(z); GATE(w);
#undef GATE
        h4[j4]  = hn;
        cn4[j4] = cn;
    }
}

// ---------------------------------------------------------------------------
extern "C" void kernel_launch(void* const* d_in, const int* in_sizes, int n_in,
                              void* d_out, int out_size)
{
    // metadata order: x(0, unused), h(1), c(2), W(3), b(4), gn_weight(5), gn_bias(6)
    const float* h  = (const float*)d_in[1];
    const float* c  = (const float*)d_in[2];
    const float* W  = (const float*)d_in[3];
    const float* b  = (const float*)d_in[4];
    const float* gw = (const float*)d_in[5];
    const float* gb = (const float*)d_in[6];
    float* out = (float*)d_out;

    float* z;          cudaGetSymbolAddress((void**)&z, g_z);
    __half *Ah, *Bh;
    cudaGetSymbolAddress((void**)&Ah, g_Ah);
    cudaGetSymbolAddress((void**)&Bh, g_Bh);

    cudaFuncSetAttribute(gemm_tc_kernel,
                         cudaFuncAttributeMaxDynamicSharedMemorySize, SMEM_TOTAL);

    const int nA4 = Bdim * Kdim / 4;
    const int nB4 = Ndim * Kdim / 4;
    cvt_fp16_kernel<<<(nA4 + 255) / 256, 256>>>(h, Ah, nA4);
    cvt_fp16_kernel<<<(nB4 + 255) / 256, 256>>>(W, Bh, nB4);

    dim3 ggrid(Ndim / BN, Bdim / BM);   // (64, 32)
    gemm_tc_kernel<<<ggrid, 256, SMEM_TOTAL>>>(Ah, Bh, b, z);

    gn_gates_kernel<<<Bdim, 256>>>(z, c, gw, gb, out);
}

// round 8
// speedup vs baseline: 5.6355x; 1.0074x over previous
#include <cuda_runtime.h>
#include <cuda_fp16.h>
#include <math.h>
#include <stdint.h>

// ---------------------------------------------------------------------------
// Problem dims
#define Bdim 4096
#define Hdim 2048
#define Ndim 8192   // 4*H
#define Kdim 2048

// GEMM tiling
#define BM 128
#define BN 128
#define BK 32
#define STAGES 5
#define NT (Kdim / BK)      // 64

// SMEM stage layout (rows of 40 fp16 = 80B; pad 32->40 for conflict-free ldmatrix)
#define RSB  80
#define STG_A 0
#define STG_B 10240
#define STG_SIZE 20480
#define SMEM_TOTAL (STAGES * STG_SIZE)   // 102400 per CTA -> 2 CTAs/SM

// Scratch (static device arrays; no runtime allocation allowed)
__device__ __half g_zh[(size_t)Bdim * Ndim];   // z in fp16 (64 MB)
__device__ __half g_Ah[(size_t)Bdim * Kdim];
__device__ __half g_Bh[(size_t)Ndim * Kdim];

// ---------------------------------------------------------------------------
__device__ __forceinline__ uint32_t smem_u32(const void* p) {
    uint32_t a;
    asm("{ .reg .u64 t; cvta.to.shared.u64 t, %1; cvt.u32.u64 %0, t; }" : "=r"(a) : "l"(p));
    return a;
}
__device__ __forceinline__ void cp16(uint32_t dst, const void* src) {
    asm volatile("cp.async.cg.shared.global [%0], [%1], 16;\n" :: "r"(dst), "l"(src) : "memory");
}
#define CP_COMMIT()  asm volatile("cp.async.commit_group;" ::: "memory")
#define CP_WAIT(n)   asm volatile("cp.async.wait_group %0;" :: "n"(n) : "memory")

#define LDSM4(r0, r1, r2, r3, addr)                                           \
    asm volatile("ldmatrix.sync.aligned.m8n8.x4.shared.b16 {%0,%1,%2,%3},[%4];" \
        : "=r"(r0), "=r"(r1), "=r"(r2), "=r"(r3) : "r"(addr))

#define MMA_F16(d, a, b0, b1)                                                 \
    asm volatile("mma.sync.aligned.m16n8k16.row.col.f32.f16.f16.f32 "         \
        "{%0,%1,%2,%3},{%4,%5,%6,%7},{%8,%9},{%0,%1,%2,%3};"                  \
        : "+f"((d)[0]), "+f"((d)[1]), "+f"((d)[2]), "+f"((d)[3])              \
        : "r"((a)[0]), "r"((a)[1]), "r"((a)[2]), "r"((a)[3]),                 \
          "r"(b0), "r"(b1))

// ---------------------------------------------------------------------------
// Kernel 0: convert fp32 -> fp16
// ---------------------------------------------------------------------------
__global__ __launch_bounds__(256) void cvt_fp16_kernel(
    const float* __restrict__ x, __half* __restrict__ y, int n4)
{
    int i = blockIdx.x * blockDim.x + threadIdx.x;
    if (i >= n4) return;
    float4 v = ((const float4*)x)[i];
    __half2 a, b;
    a.x = __float2half_rn(v.x); a.y = __float2half_rn(v.y);
    b.x = __float2half_rn(v.z); b.y = __float2half_rn(v.w);
    ((__half2*)y)[2 * i]     = a;
    ((__half2*)y)[2 * i + 1] = b;
}

// ---------------------------------------------------------------------------
// Kernel 1: z[M,N] = A[M,K] @ B[N,K]^T + bias   (fp16 in, fp32 accum, fp16 z out)
// 256 threads = 8 warps in 2(M) x 4(N); per warp 64x32.  2 CTAs/SM.
// ---------------------------------------------------------------------------
__global__ __launch_bounds__(256, 2) void gemm_tc_kernel(
    const __half* __restrict__ A, const __half* __restrict__ B,
    const float* __restrict__ bias, __half* __restrict__ Z)
{
    extern __shared__ char smem[];
    const uint32_t sb = smem_u32(smem);

    const int tid    = threadIdx.x;
    const int lane   = tid & 31;
    const int wid    = tid >> 5;
    const int warp_m = wid & 1;     // 0..1 -> 64 rows each
    const int warp_n = wid >> 1;    // 0..3 -> 32 cols each
    const int bm     = blockIdx.y * BM;
    const int bn     = blockIdx.x * BN;

    const char* Ag = (const char*)(A + (size_t)bm * Kdim);
    const char* Bg = (const char*)(B + (size_t)bn * Kdim);

    const int lc = (tid & 3) * 16;
    const int lr = tid >> 2;        // 0..63

    uint32_t offA[4];
#pragma unroll
    for (int mt = 0; mt < 4; mt++)
        offA[mt] = (uint32_t)((warp_m * 64 + mt * 16 + (lane & 15)) * RSB + (lane >> 4) * 16);
    uint32_t offB[2];
#pragma unroll
    for (int pr = 0; pr < 2; pr++)
        offB[pr] = (uint32_t)((warp_n * 32 + pr * 16 + (lane & 7) + ((lane >> 4) & 1) * 8) * RSB
                              + ((lane >> 3) & 1) * 16);

    float acc[4][4][4];
#pragma unroll
    for (int mt = 0; mt < 4; mt++)
#pragma unroll
        for (int nt = 0; nt < 4; nt++)
#pragma unroll
            for (int q = 0; q < 4; q++) acc[mt][nt][q] = 0.f;

    // -------- pipeline prologue --------
#pragma unroll
    for (int t = 0; t < STAGES - 1; t++) {
        const uint32_t st = sb + t * STG_SIZE;
        const size_t kb = (size_t)t * (BK * 2);
#pragma unroll
        for (int p = 0; p < 2; p++) {
            const int r = lr + p * 64;
            cp16(st + STG_A + r * RSB + lc, Ag + (size_t)r * (Kdim * 2) + kb + lc);
            cp16(st + STG_B + r * RSB + lc, Bg + (size_t)r * (Kdim * 2) + kb + lc);
        }
        CP_COMMIT();
    }

    // -------- main loop --------
    for (int t = 0; t < NT; t++) {
        CP_WAIT(STAGES - 2);
        __syncthreads();

        const int tn = t + STAGES - 1;
        if (tn < NT) {
            const uint32_t st = sb + (tn % STAGES) * STG_SIZE;
            const size_t kb = (size_t)tn * (BK * 2);
#pragma unroll
            for (int p = 0; p < 2; p++) {
                const int r = lr + p * 64;
                cp16(st + STG_A + r * RSB + lc, Ag + (size_t)r * (Kdim * 2) + kb + lc);
                cp16(st + STG_B + r * RSB + lc, Bg + (size_t)r * (Kdim * 2) + kb + lc);
            }
        }
        CP_COMMIT();

        const uint32_t st = sb + (t % STAGES) * STG_SIZE;
#pragma unroll
        for (int ks = 0; ks < 2; ks++) {
            const uint32_t ko = ks * 32;
            uint32_t ah[4][4];
#pragma unroll
            for (int mt = 0; mt < 4; mt++)
                LDSM4(ah[mt][0], ah[mt][1], ah[mt][2], ah[mt][3], st + STG_A + offA[mt] + ko);
#pragma unroll
            for (int pr = 0; pr < 2; pr++) {
                uint32_t bh[4];
                LDSM4(bh[0], bh[1], bh[2], bh[3], st + STG_B + offB[pr] + ko);
#pragma unroll
                for (int sub = 0; sub < 2; sub++) {
                    const int nt = pr * 2 + sub;
#pragma unroll
                    for (int mt = 0; mt < 4; mt++)
                        MMA_F16(acc[mt][nt], ah[mt], bh[2 * sub], bh[2 * sub + 1]);
                }
            }
        }
    }

    // -------- epilogue: bias add + fp16 store --------
    const int ln4 = lane >> 2;
    const int lq  = lane & 3;
#pragma unroll
    for (int mt = 0; mt < 4; mt++) {
#pragma unroll
        for (int nt = 0; nt < 4; nt++) {
            const int m0 = bm + warp_m * 64 + mt * 16 + ln4;
            const int n  = bn + warp_n * 32 + nt * 8 + lq * 2;
            const float2 bv = *(const float2*)(bias + n);
            __half2 o0 = __floats2half2_rn(acc[mt][nt][0] + bv.x, acc[mt][nt][1] + bv.y);
            __half2 o1 = __floats2half2_rn(acc[mt][nt][2] + bv.x, acc[mt][nt][3] + bv.y);
            *(__half2*)(Z + (size_t)m0 * Ndim + n)       = o0;
            *(__half2*)(Z + (size_t)(m0 + 8) * Ndim + n) = o1;
        }
    }
}

// ---------------------------------------------------------------------------
// Kernel 2: per-row GroupNorm(4 groups of 2048) + LSTM gates, fp16 z input
// ---------------------------------------------------------------------------
__device__ __forceinline__ float sigmoidf_(float x) {
    return 1.f / (1.f + expf(-x));
}

__global__ __launch_bounds__(256) void gn_gates_kernel(
    const __half* __restrict__ z, const float* __restrict__ cin,
    const float* __restrict__ gw, const float* __restrict__ gb,
    float* __restrict__ out)
{
    __shared__ uint4 zs[1024];           // full z row in fp16 (16 KB); 8 halves per uint4
    __shared__ float red_s[256], red_q[256];
    __shared__ float s_mean[4], s_rstd[4];

    const int r = blockIdx.x;
    const int t = threadIdx.x;
    const uint4* z8 = (const uint4*)(z + (size_t)r * Ndim);  // 1024 x 8 halves

    // --- Phase 1: per-group stats. group g owns uint4 [g*256, (g+1)*256) ---
    const int g    = t >> 6;
    const int lane = t & 63;
    float s = 0.f, ss = 0.f;
#pragma unroll
    for (int i = 0; i < 4; i++) {
        const int idx = g * 256 + lane + i * 64;
        uint4 v = z8[idx];
        zs[idx] = v;
        const __half2* hp = (const __half2*)&v;
#pragma unroll
        for (int q = 0; q < 4; q++) {
            float2 f = __half22float2(hp[q]);
            s  += f.x + f.y;
            ss += f.x * f.x + f.y * f.y;
        }
    }
    red_s[t] = s; red_q[t] = ss;
    __syncthreads();
#pragma unroll
    for (int off = 32; off >= 1; off >>= 1) {
        if (lane < off) {
            red_s[t] += red_s[t + off];
            red_q[t] += red_q[t + off];
        }
        __syncthreads();
    }
    if (t < 4) {
        float m = red_s[t * 64] * (1.f / 2048.f);
        float v = red_q[t * 64] * (1.f / 2048.f) - m * m;
        s_mean[t] = m;
        s_rstd[t] = rsqrtf(v + 1e-5f);
    }
    __syncthreads();

    const float mi = s_mean[0], ri = s_rstd[0];
    const float mf = s_mean[1], rf = s_rstd[1];
    const float mo = s_mean[2], ro = s_rstd[2];
    const float mg = s_mean[3], rg = s_rstd[3];

    const float4* c4  = (const float4*)(cin + (size_t)r * Hdim);
    const float4* gw4 = (const float4*)gw;
    const float4* gb4 = (const float4*)gb;
    float4* h4  = (float4*)out + (size_t)r * (Hdim / 4);
    float4* cn4 = (float4*)out + (size_t)Bdim * (Hdim / 4) + (size_t)r * (Hdim / 4);
    const uint2* zs2 = (const uint2*)zs;   // 4 halves per uint2; 2048 per row

    // --- Phase 2: gates; each thread 2 chunks of 4 channels ---
#pragma unroll
    for (int p = 0; p < 2; p++) {
        const int j4 = t + p * 256;   // 0..511 over H/4
        uint2 pi = zs2[j4];
        uint2 pf = zs2[512 + j4];
        uint2 po = zs2[1024 + j4];
        uint2 pg = zs2[1536 + j4];
        float2 zi01 = __half22float2(*(__half2*)&pi.x), zi23 = __half22float2(*(__half2*)&pi.y);
        float2 zf01 = __half22float2(*(__half2*)&pf.x), zf23 = __half22float2(*(__half2*)&pf.y);
        float2 zo01 = __half22float2(*(__half2*)&po.x), zo23 = __half22float2(*(__half2*)&po.y);
        float2 zg01 = __half22float2(*(__half2*)&pg.x), zg23 = __half22float2(*(__half2*)&pg.y);
        float4 zi = make_float4(zi01.x, zi01.y, zi23.x, zi23.y);
        float4 zf = make_float4(zf01.x, zf01.y, zf23.x, zf23.y);
        float4 zo = make_float4(zo01.x, zo01.y, zo23.x, zo23.y);
        float4 zg = make_float4(zg01.x, zg01.y, zg23.x, zg23.y);

        float4 wi = gw4[j4],        bi  = gb4[j4];
        float4 wf = gw4[512 + j4],  bf2 = gb4[512 + j4];
        float4 wo = gw4[1024 + j4], bo  = gb4[1024 + j4];
        float4 wg = gw4[1536 + j4], bg  = gb4[1536 + j4];
        float4 cv = c4[j4];

        float4 hn, cn;
#define GATE(comp)                                                            \
        {                                                                     \
            float vi = (zi.comp - mi) * ri * wi.comp + bi.comp;               \
            float vf = (zf.comp - mf) * rf * wf.comp + bf2.comp;              \
            float vo = (zo.comp - mo) * ro * wo.comp + bo.comp;               \
            float vg = (zg.comp - mg) * rg * wg.comp + bg.comp;               \
            float cnew = sigmoidf_(vf) * cv.comp + sigmoidf_(vi) * tanhf(vg); \
            cn.comp = cnew;                                                   \
            hn.comp = sigmoidf_(vo) * tanhf(cnew);                            \
        }
        GATE(x); GATE(y); GATE(z); GATE(w);
#undef GATE
        h4[j4]  = hn;
        cn4[j4] = cn;
    }
}

// ---------------------------------------------------------------------------
extern "C" void kernel_launch(void* const* d_in, const int* in_sizes, int n_in,
                              void* d_out, int out_size)
{
    // metadata order: x(0, unused), h(1), c(2), W(3), b(4), gn_weight(5), gn_bias(6)
    const float* h  = (const float*)d_in[1];
    const float* c  = (const float*)d_in[2];
    const float* W  = (const float*)d_in[3];
    const float* b  = (const float*)d_in[4];
    const float* gw = (const float*)d_in[5];
    const float* gb = (const float*)d_in[6];
    float* out = (float*)d_out;

    __half *z, *Ah, *Bh;
    cudaGetSymbolAddress((void**)&z,  g_zh);
    cudaGetSymbolAddress((void**)&Ah, g_Ah);
    cudaGetSymbolAddress((void**)&Bh, g_Bh);

    cudaFuncSetAttribute(gemm_tc_kernel,
                         cudaFuncAttributeMaxDynamicSharedMemorySize, SMEM_TOTAL);

    const int nA4 = Bdim * Kdim / 4;
    const int nB4 = Ndim * Kdim / 4;
    cvt_fp16_kernel<<<(nA4 + 255) / 256, 256>>>(h, Ah, nA4);
    cvt_fp16_kernel<<<(nB4 + 255) / 256, 256>>>(W, Bh, nB4);

    dim3 ggrid(Ndim / BN, Bdim / BM);   // (64, 32)
    gemm_tc_kernel<<<ggrid, 256, SMEM_TOTAL>>>(Ah, Bh, b, z);

    gn_gates_kernel<<<Bdim, 256>>>(z, c, gw, gb, out);
}